// round 1
// baseline (speedup 1.0000x reference)
#include <cuda_runtime.h>
#include <math.h>
#include <stdint.h>

#define D_MODEL 1024
#define N_HEADS 16
#define HEAD_DIM 64
#define BATCH 4
#define SEQ 2048
#define M_TOK (BATCH * SEQ) /* 8192 */

// ---------------- scratch (allocation-free: __device__ globals) ----------------
__device__ float g_q[(size_t)M_TOK * D_MODEL];
__device__ float g_k[(size_t)M_TOK * D_MODEL];
__device__ float g_v[(size_t)M_TOK * D_MODEL];
__device__ float g_attn[(size_t)M_TOK * D_MODEL];
__device__ float g_t[(size_t)M_TOK * D_MODEL];
__device__ float g_cat[(size_t)M_TOK * 2 * D_MODEL];

// ---------------- GEMM: C[M,N] = A[M,K] @ W[K,N] + bias (+epilogue) ----------------
// EPI: 0 = bias only, 1 = bias + residual add, 2 = bias + exact GELU
// 128x128 block tile, BK=8, 256 threads, 8x8 per thread (split 4+4 rows/cols
// 64 apart so shared loads are conflict-free float4).
template <int EPI>
__global__ __launch_bounds__(256, 2) void sgemm_epi(
    const float* __restrict__ A, const float* __restrict__ W,
    const float* __restrict__ bias, const float* __restrict__ resid,
    float* __restrict__ C, int M, int N, int K)
{
    __shared__ float As[8][128];
    __shared__ float Bs[8][128];

    const int tid  = threadIdx.x;
    const int brow = blockIdx.y * 128;
    const int bcol = blockIdx.x * 128;
    const int ty = tid >> 4;   // 0..15
    const int tx = tid & 15;   // 0..15

    // A tile loader: 128 rows x 8 cols, one float4 per thread
    const int arow = tid >> 1;           // 0..127
    const int acol = (tid & 1) * 4;      // 0 or 4
    // W tile loader: 8 rows x 128 cols, one float4 per thread
    const int wrow = tid >> 5;           // 0..7
    const int wcol = (tid & 31) * 4;     // 0..124

    float acc[8][8];
#pragma unroll
    for (int i = 0; i < 8; i++)
#pragma unroll
        for (int j = 0; j < 8; j++) acc[i][j] = 0.0f;

    const float* Aptr = A + (size_t)(brow + arow) * K + acol;
    const float* Wptr = W + (size_t)wrow * N + bcol + wcol;

    for (int k0 = 0; k0 < K; k0 += 8) {
        float4 av = *(const float4*)(Aptr + k0);
        float4 wv = *(const float4*)(Wptr + (size_t)k0 * N);
        As[acol + 0][arow] = av.x;
        As[acol + 1][arow] = av.y;
        As[acol + 2][arow] = av.z;
        As[acol + 3][arow] = av.w;
        *(float4*)&Bs[wrow][wcol] = wv;
        __syncthreads();

#pragma unroll
        for (int kk = 0; kk < 8; kk++) {
            float ar[8], br[8];
            float4 a0 = *(const float4*)&As[kk][ty * 4];
            float4 a1 = *(const float4*)&As[kk][64 + ty * 4];
            float4 b0 = *(const float4*)&Bs[kk][tx * 4];
            float4 b1 = *(const float4*)&Bs[kk][64 + tx * 4];
            ar[0] = a0.x; ar[1] = a0.y; ar[2] = a0.z; ar[3] = a0.w;
            ar[4] = a1.x; ar[5] = a1.y; ar[6] = a1.z; ar[7] = a1.w;
            br[0] = b0.x; br[1] = b0.y; br[2] = b0.z; br[3] = b0.w;
            br[4] = b1.x; br[5] = b1.y; br[6] = b1.z; br[7] = b1.w;
#pragma unroll
            for (int i = 0; i < 8; i++)
#pragma unroll
                for (int j = 0; j < 8; j++)
                    acc[i][j] = fmaf(ar[i], br[j], acc[i][j]);
        }
        __syncthreads();
    }

    // epilogue
#pragma unroll
    for (int i = 0; i < 8; i++) {
        const int r = brow + ((i < 4) ? (ty * 4 + i) : (64 + ty * 4 + (i - 4)));
#pragma unroll
        for (int g = 0; g < 2; g++) {
            const int c = bcol + g * 64 + tx * 4;
            float4 bv = *(const float4*)(bias + c);
            float4 v;
            v.x = acc[i][g * 4 + 0] + bv.x;
            v.y = acc[i][g * 4 + 1] + bv.y;
            v.z = acc[i][g * 4 + 2] + bv.z;
            v.w = acc[i][g * 4 + 3] + bv.w;
            if (EPI == 1) {
                float4 rv = *(const float4*)(resid + (size_t)r * N + c);
                v.x += rv.x; v.y += rv.y; v.z += rv.z; v.w += rv.w;
            }
            if (EPI == 2) {
                v.x = 0.5f * v.x * (1.0f + erff(v.x * 0.7071067811865475f));
                v.y = 0.5f * v.y * (1.0f + erff(v.y * 0.7071067811865475f));
                v.z = 0.5f * v.z * (1.0f + erff(v.z * 0.7071067811865475f));
                v.w = 0.5f * v.w * (1.0f + erff(v.w * 0.7071067811865475f));
            }
            *(float4*)(C + (size_t)r * N + c) = v;
        }
    }
}

// ---------------- Attention (two-pass softmax, per-thread query row) ----------------
// Q,K,V,O layouts: [B, T, D] with head h occupying columns [h*64, h*64+64).
// Block = 64 threads, each thread owns one query row; 64-key tiles staged in smem.
__global__ __launch_bounds__(64) void attn_kernel(
    const float* __restrict__ Q, const float* __restrict__ K,
    const float* __restrict__ V, float* __restrict__ O)
{
    __shared__ float Ks[64][64];
    __shared__ float Vs[64][64];

    const int tid = threadIdx.x;
    const int b = blockIdx.z;
    const int h = blockIdx.y;
    const int q0 = blockIdx.x * 64;

    const size_t hoff = (size_t)h * HEAD_DIM;
    const float* Qrow = Q + ((size_t)(b * SEQ + q0 + tid)) * D_MODEL + hoff;
    const float* Kbase = K + ((size_t)b * SEQ) * D_MODEL + hoff;
    const float* Vbase = V + ((size_t)b * SEQ) * D_MODEL + hoff;

    float qr[64];
#pragma unroll
    for (int d4 = 0; d4 < 16; d4++) {
        float4 t = *(const float4*)(Qrow + d4 * 4);
        qr[d4 * 4 + 0] = t.x * 0.125f;  // 1/sqrt(64)
        qr[d4 * 4 + 1] = t.y * 0.125f;
        qr[d4 * 4 + 2] = t.z * 0.125f;
        qr[d4 * 4 + 3] = t.w * 0.125f;
    }

    // ---- pass 1: global max of scores ----
    float m = -1e30f;
    for (int kt = 0; kt < SEQ; kt += 64) {
#pragma unroll
        for (int it = 0; it < 16; it++) {
            int idx = it * 64 + tid;
            int jr = idx >> 4;
            int c4 = (idx & 15) * 4;
            *(float4*)&Ks[jr][c4] =
                *(const float4*)(Kbase + (size_t)(kt + jr) * D_MODEL + c4);
        }
        __syncthreads();
#pragma unroll 2
        for (int j = 0; j < 64; j++) {
            const float4* kr = (const float4*)Ks[j];
            float s = 0.0f;
#pragma unroll
            for (int d4 = 0; d4 < 16; d4++) {
                float4 kk = kr[d4];
                s = fmaf(qr[d4 * 4 + 0], kk.x, s);
                s = fmaf(qr[d4 * 4 + 1], kk.y, s);
                s = fmaf(qr[d4 * 4 + 2], kk.z, s);
                s = fmaf(qr[d4 * 4 + 3], kk.w, s);
            }
            m = fmaxf(m, s);
        }
        __syncthreads();
    }

    // ---- pass 2: exp/accumulate ----
    float l = 0.0f;
    float o[64];
#pragma unroll
    for (int d = 0; d < 64; d++) o[d] = 0.0f;

    for (int kt = 0; kt < SEQ; kt += 64) {
#pragma unroll
        for (int it = 0; it < 16; it++) {
            int idx = it * 64 + tid;
            int jr = idx >> 4;
            int c4 = (idx & 15) * 4;
            *(float4*)&Ks[jr][c4] =
                *(const float4*)(Kbase + (size_t)(kt + jr) * D_MODEL + c4);
            *(float4*)&Vs[jr][c4] =
                *(const float4*)(Vbase + (size_t)(kt + jr) * D_MODEL + c4);
        }
        __syncthreads();
#pragma unroll 2
        for (int j = 0; j < 64; j++) {
            const float4* kr = (const float4*)Ks[j];
            float s = 0.0f;
#pragma unroll
            for (int d4 = 0; d4 < 16; d4++) {
                float4 kk = kr[d4];
                s = fmaf(qr[d4 * 4 + 0], kk.x, s);
                s = fmaf(qr[d4 * 4 + 1], kk.y, s);
                s = fmaf(qr[d4 * 4 + 2], kk.z, s);
                s = fmaf(qr[d4 * 4 + 3], kk.w, s);
            }
            float p = __expf(s - m);
            l += p;
            const float4* vr = (const float4*)Vs[j];
#pragma unroll
            for (int d4 = 0; d4 < 16; d4++) {
                float4 vv = vr[d4];
                o[d4 * 4 + 0] = fmaf(p, vv.x, o[d4 * 4 + 0]);
                o[d4 * 4 + 1] = fmaf(p, vv.y, o[d4 * 4 + 1]);
                o[d4 * 4 + 2] = fmaf(p, vv.z, o[d4 * 4 + 2]);
                o[d4 * 4 + 3] = fmaf(p, vv.w, o[d4 * 4 + 3]);
            }
        }
        __syncthreads();
    }

    const float inv = 1.0f / l;
    float* Orow = O + ((size_t)(b * SEQ + q0 + tid)) * D_MODEL + hoff;
#pragma unroll
    for (int d4 = 0; d4 < 16; d4++) {
        float4 t;
        t.x = o[d4 * 4 + 0] * inv;
        t.y = o[d4 * 4 + 1] * inv;
        t.z = o[d4 * 4 + 2] * inv;
        t.w = o[d4 * 4 + 3] * inv;
        *(float4*)(Orow + d4 * 4) = t;
    }
}

// ---------------- LayerNorm over last dim (1024), one block per row ----------------
__global__ __launch_bounds__(256) void ln_kernel(
    const float* __restrict__ x, const float* __restrict__ w,
    const float* __restrict__ b, float* __restrict__ out, int ldo)
{
    const int row = blockIdx.x;
    const int tid = threadIdx.x;

    float4 v = ((const float4*)(x + (size_t)row * D_MODEL))[tid];
    float s  = v.x + v.y + v.z + v.w;
    float s2 = v.x * v.x + v.y * v.y + v.z * v.z + v.w * v.w;

#pragma unroll
    for (int off = 16; off > 0; off >>= 1) {
        s  += __shfl_xor_sync(0xffffffffu, s, off);
        s2 += __shfl_xor_sync(0xffffffffu, s2, off);
    }
    __shared__ float rs[8], rs2[8];
    __shared__ float smu, sinv;
    const int wid = tid >> 5;
    if ((tid & 31) == 0) { rs[wid] = s; rs2[wid] = s2; }
    __syncthreads();
    if (tid == 0) {
        float ts = 0.0f, ts2 = 0.0f;
#pragma unroll
        for (int i = 0; i < 8; i++) { ts += rs[i]; ts2 += rs2[i]; }
        float mu  = ts * (1.0f / D_MODEL);
        float var = ts2 * (1.0f / D_MODEL) - mu * mu;
        smu = mu;
        sinv = rsqrtf(var + 1e-5f);
    }
    __syncthreads();
    const float mu = smu, inv = sinv;

    float4 wv = ((const float4*)w)[tid];
    float4 bv = ((const float4*)b)[tid];
    float4 ov;
    ov.x = (v.x - mu) * inv * wv.x + bv.x;
    ov.y = (v.y - mu) * inv * wv.y + bv.y;
    ov.z = (v.z - mu) * inv * wv.z + bv.z;
    ov.w = (v.w - mu) * inv * wv.w + bv.w;
    ((float4*)(out + (size_t)row * ldo))[tid] = ov;
}

// ---------------- orchestration ----------------
extern "C" void kernel_launch(void* const* d_in, const int* in_sizes, int n_in,
                              void* d_out, int out_size)
{
    (void)in_sizes; (void)n_in; (void)out_size;

    const float* temporal = (const float*)d_in[0];
    const float* feature  = (const float*)d_in[1];
    const float* qt_w = (const float*)d_in[2];  const float* qt_b = (const float*)d_in[3];
    const float* kf_w = (const float*)d_in[4];  const float* kf_b = (const float*)d_in[5];
    const float* vf_w = (const float*)d_in[6];  const float* vf_b = (const float*)d_in[7];
    const float* qf_w = (const float*)d_in[8];  const float* qf_b = (const float*)d_in[9];
    const float* kt_w = (const float*)d_in[10]; const float* kt_b = (const float*)d_in[11];
    const float* vt_w = (const float*)d_in[12]; const float* vt_b = (const float*)d_in[13];
    const float* ot_w = (const float*)d_in[14]; const float* ot_b = (const float*)d_in[15];
    const float* of_w = (const float*)d_in[16]; const float* of_b = (const float*)d_in[17];
    const float* fus1_w = (const float*)d_in[18]; const float* fus1_b = (const float*)d_in[19];
    const float* fus2_w = (const float*)d_in[20]; const float* fus2_b = (const float*)d_in[21];
    const float* ln_fus_w = (const float*)d_in[22]; const float* ln_fus_b = (const float*)d_in[23];
    const float* ln_t_w = (const float*)d_in[24]; const float* ln_t_b = (const float*)d_in[25];
    const float* ln_f_w = (const float*)d_in[26]; const float* ln_f_b = (const float*)d_in[27];
    float* out = (float*)d_out;

    float *q, *k, *v, *attn, *t, *cat;
    cudaGetSymbolAddress((void**)&q,    g_q);
    cudaGetSymbolAddress((void**)&k,    g_k);
    cudaGetSymbolAddress((void**)&v,    g_v);
    cudaGetSymbolAddress((void**)&attn, g_attn);
    cudaGetSymbolAddress((void**)&t,    g_t);
    cudaGetSymbolAddress((void**)&cat,  g_cat);

    const dim3 ggrid(D_MODEL / 128, M_TOK / 128);  // (8, 64)
    const dim3 agrid(SEQ / 64, N_HEADS, BATCH);    // (32, 16, 4)

    // temporal -> feature cross attention
    sgemm_epi<0><<<ggrid, 256>>>(temporal, qt_w, qt_b, nullptr, q, M_TOK, D_MODEL, D_MODEL);
    sgemm_epi<0><<<ggrid, 256>>>(feature,  kf_w, kf_b, nullptr, k, M_TOK, D_MODEL, D_MODEL);
    sgemm_epi<0><<<ggrid, 256>>>(feature,  vf_w, vf_b, nullptr, v, M_TOK, D_MODEL, D_MODEL);
    attn_kernel<<<agrid, 64>>>(q, k, v, attn);
    sgemm_epi<1><<<ggrid, 256>>>(attn, ot_w, ot_b, temporal, t, M_TOK, D_MODEL, D_MODEL);
    ln_kernel<<<M_TOK, 256>>>(t, ln_t_w, ln_t_b, cat, 2 * D_MODEL);

    // feature -> temporal cross attention
    sgemm_epi<0><<<ggrid, 256>>>(feature,  qf_w, qf_b, nullptr, q, M_TOK, D_MODEL, D_MODEL);
    sgemm_epi<0><<<ggrid, 256>>>(temporal, kt_w, kt_b, nullptr, k, M_TOK, D_MODEL, D_MODEL);
    sgemm_epi<0><<<ggrid, 256>>>(temporal, vt_w, vt_b, nullptr, v, M_TOK, D_MODEL, D_MODEL);
    attn_kernel<<<agrid, 64>>>(q, k, v, attn);
    sgemm_epi<1><<<ggrid, 256>>>(attn, of_w, of_b, feature, t, M_TOK, D_MODEL, D_MODEL);
    ln_kernel<<<M_TOK, 256>>>(t, ln_f_w, ln_f_b, cat + D_MODEL, 2 * D_MODEL);

    // fusion MLP
    sgemm_epi<2><<<ggrid, 256>>>(cat, fus1_w, fus1_b, nullptr, q, M_TOK, D_MODEL, 2 * D_MODEL);
    sgemm_epi<0><<<ggrid, 256>>>(q,   fus2_w, fus2_b, nullptr, t, M_TOK, D_MODEL, D_MODEL);
    ln_kernel<<<M_TOK, 256>>>(t, ln_fus_w, ln_fus_b, out, D_MODEL);
}

// round 2
// speedup vs baseline: 2.8227x; 2.8227x over previous
#include <cuda_runtime.h>
#include <cuda_bf16.h>
#include <math.h>
#include <stdint.h>

#define D_MODEL 1024
#define N_HEADS 16
#define HEAD_DIM 64
#define BATCH 4
#define SEQ 2048
#define M_TOK (BATCH * SEQ) /* 8192 */

// ---------------- scratch (allocation-free: __device__ globals) ----------------
__device__ float g_q[(size_t)M_TOK * D_MODEL];
__device__ float g_k[(size_t)M_TOK * D_MODEL];
__device__ float g_v[(size_t)M_TOK * D_MODEL];
__device__ float g_attn[(size_t)M_TOK * D_MODEL];
__device__ float g_t[(size_t)M_TOK * D_MODEL];
__device__ float g_cat[(size_t)M_TOK * 2 * D_MODEL];

// ---------------- helpers ----------------
__device__ __forceinline__ void split_pk(float a, float b, unsigned &hi, unsigned &lo) {
    // pack (a -> low 16, b -> high 16) as bf16 hi parts, and bf16 of residuals as lo
    __nv_bfloat16 ah = __float2bfloat16_rn(a);
    __nv_bfloat16 bh = __float2bfloat16_rn(b);
    hi = ((unsigned)__bfloat16_as_ushort(bh) << 16) | (unsigned)__bfloat16_as_ushort(ah);
    float ar = a - __bfloat162float(ah);
    float br = b - __bfloat162float(bh);
    lo = ((unsigned)__bfloat16_as_ushort(__float2bfloat16_rn(br)) << 16) |
         (unsigned)__bfloat16_as_ushort(__float2bfloat16_rn(ar));
}

__device__ __forceinline__ void mma16816(float* d, unsigned a0, unsigned a1,
                                         unsigned a2, unsigned a3,
                                         unsigned b0, unsigned b1) {
    asm volatile(
        "mma.sync.aligned.m16n8k16.row.col.f32.bf16.bf16.f32 "
        "{%0,%1,%2,%3},{%4,%5,%6,%7},{%8,%9},{%0,%1,%2,%3};"
        : "+f"(d[0]), "+f"(d[1]), "+f"(d[2]), "+f"(d[3])
        : "r"(a0), "r"(a1), "r"(a2), "r"(a3), "r"(b0), "r"(b1));
}

// ---------------- split-bf16 tensor-core GEMM ----------------
// C[M,N] = A[M,K] @ W[K,N] + bias (+epilogue). EPI: 0 bias, 1 bias+resid, 2 bias+GELU
// 128x128 block, BK=32, 256 threads (8 warps, 4x2), warp tile 32x64.
template <int EPI>
__global__ __launch_bounds__(256) void tgemm_epi(
    const float* __restrict__ A, const float* __restrict__ W,
    const float* __restrict__ bias, const float* __restrict__ resid,
    float* __restrict__ C, int M, int N, int K)
{
    __shared__ struct alignas(16) {
        unsigned Ahi[128][18], Alo[128][18];   // pair-packed along k (BK/2=16 + pad2)
        unsigned Bhi[16][132], Blo[16][132];   // pair rows (k/2), n cols + pad4
    } sm;

    const int tid = threadIdx.x;
    const int lane = tid & 31;
    const int wid = tid >> 5;
    const int warpM = wid & 3;     // 0..3 -> 32-row slices
    const int warpN = wid >> 2;    // 0..1 -> 64-col slices
    const int brow = blockIdx.y * 128;
    const int bcol = blockIdx.x * 128;

    float acc[2][8][4];
#pragma unroll
    for (int mt = 0; mt < 2; mt++)
#pragma unroll
        for (int nt = 0; nt < 8; nt++)
#pragma unroll
            for (int i = 0; i < 4; i++) acc[mt][nt][i] = 0.0f;

    for (int k0 = 0; k0 < K; k0 += 32) {
        __syncthreads();
        // ---- load A tile (128 x 32 fp32 -> split bf16 pairs) ----
        {
            const int m = tid >> 1;
            const int kb = (tid & 1) * 16;
            const float* ap = A + (size_t)(brow + m) * K + k0 + kb;
#pragma unroll
            for (int q = 0; q < 4; q++) {
                float4 v = *(const float4*)(ap + q * 4);
                unsigned h0, l0, h1, l1;
                split_pk(v.x, v.y, h0, l0);
                split_pk(v.z, v.w, h1, l1);
                const int c = (kb + q * 4) >> 1;
                sm.Ahi[m][c] = h0; sm.Ahi[m][c + 1] = h1;
                sm.Alo[m][c] = l0; sm.Alo[m][c + 1] = l1;
            }
        }
        // ---- load W tile (32 x 128 fp32 -> pair-packed along k) ----
        {
            const int p = tid >> 4;            // k-pair row 0..15
            const int n8 = (tid & 15) * 8;
            const float* w0 = W + (size_t)(k0 + 2 * p) * N + bcol + n8;
            const float* w1 = w0 + N;
#pragma unroll
            for (int q = 0; q < 2; q++) {
                float4 u = *(const float4*)(w0 + q * 4);
                float4 v = *(const float4*)(w1 + q * 4);
                unsigned h, l;
                split_pk(u.x, v.x, h, l); sm.Bhi[p][n8 + q * 4 + 0] = h; sm.Blo[p][n8 + q * 4 + 0] = l;
                split_pk(u.y, v.y, h, l); sm.Bhi[p][n8 + q * 4 + 1] = h; sm.Blo[p][n8 + q * 4 + 1] = l;
                split_pk(u.z, v.z, h, l); sm.Bhi[p][n8 + q * 4 + 2] = h; sm.Blo[p][n8 + q * 4 + 2] = l;
                split_pk(u.w, v.w, h, l); sm.Bhi[p][n8 + q * 4 + 3] = h; sm.Blo[p][n8 + q * 4 + 3] = l;
            }
        }
        __syncthreads();

#pragma unroll
        for (int ks = 0; ks < 2; ks++) {
            unsigned ah[2][4], al[2][4];
#pragma unroll
            for (int mt = 0; mt < 2; mt++) {
                const int r = warpM * 32 + mt * 16 + (lane >> 2);
                const int c = ks * 8 + (lane & 3);
                ah[mt][0] = sm.Ahi[r][c];     ah[mt][1] = sm.Ahi[r + 8][c];
                ah[mt][2] = sm.Ahi[r][c + 4]; ah[mt][3] = sm.Ahi[r + 8][c + 4];
                al[mt][0] = sm.Alo[r][c];     al[mt][1] = sm.Alo[r + 8][c];
                al[mt][2] = sm.Alo[r][c + 4]; al[mt][3] = sm.Alo[r + 8][c + 4];
            }
#pragma unroll
            for (int nt = 0; nt < 8; nt++) {
                const int n = warpN * 64 + nt * 8 + (lane >> 2);
                const int c = ks * 8 + (lane & 3);
                const unsigned bh0 = sm.Bhi[c][n], bh1 = sm.Bhi[c + 4][n];
                const unsigned bl0 = sm.Blo[c][n], bl1 = sm.Blo[c + 4][n];
#pragma unroll
                for (int mt = 0; mt < 2; mt++) {
                    mma16816(acc[mt][nt], ah[mt][0], ah[mt][1], ah[mt][2], ah[mt][3], bh0, bh1);
                    mma16816(acc[mt][nt], ah[mt][0], ah[mt][1], ah[mt][2], ah[mt][3], bl0, bl1);
                    mma16816(acc[mt][nt], al[mt][0], al[mt][1], al[mt][2], al[mt][3], bh0, bh1);
                }
            }
        }
    }

    // ---- epilogue ----
#pragma unroll
    for (int mt = 0; mt < 2; mt++) {
#pragma unroll
        for (int half = 0; half < 2; half++) {
            const int r = brow + warpM * 32 + mt * 16 + (lane >> 2) + half * 8;
#pragma unroll
            for (int nt = 0; nt < 8; nt++) {
                const int c = bcol + warpN * 64 + nt * 8 + 2 * (lane & 3);
                float x = acc[mt][nt][half * 2 + 0] + bias[c];
                float y = acc[mt][nt][half * 2 + 1] + bias[c + 1];
                if (EPI == 1) {
                    x += resid[(size_t)r * N + c];
                    y += resid[(size_t)r * N + c + 1];
                }
                if (EPI == 2) {
                    x = 0.5f * x * (1.0f + erff(x * 0.7071067811865475f));
                    y = 0.5f * y * (1.0f + erff(y * 0.7071067811865475f));
                }
                float2 o2; o2.x = x; o2.y = y;
                *(float2*)(C + (size_t)r * N + c) = o2;
            }
        }
    }
}

// ---------------- flash attention, split-bf16 mma, online softmax ----------------
// Block: 128 threads (4 warps), 64 queries x 1 head. Warp w owns query rows [16w,16w+16).
__global__ __launch_bounds__(128) void attn_mma(
    const float* __restrict__ Q, const float* __restrict__ K,
    const float* __restrict__ V, float* __restrict__ O)
{
    __shared__ union alignas(16) {
        struct { unsigned hi[64][34], lo[64][34]; } q;           // Q pairs along d
        struct { unsigned khi[32][68], klo[32][68];              // K: pair(d)/kv
                 unsigned vhi[32][68], vlo[32][68]; } kv;        // V: pair(kv)/d
    } sm;

    const int tid = threadIdx.x;
    const int lane = tid & 31;
    const int warp = tid >> 5;
    const int b = blockIdx.z;
    const int h = blockIdx.y;
    const int q0 = blockIdx.x * 64;

    const size_t hoff = (size_t)h * HEAD_DIM;
    const float* Qb = Q + ((size_t)(b * SEQ + q0)) * D_MODEL + hoff;
    const float* Kb = K + ((size_t)b * SEQ) * D_MODEL + hoff;
    const float* Vb = V + ((size_t)b * SEQ) * D_MODEL + hoff;

    // ---- stage Q (scaled) into smem as split pairs ----
    {
        const int qi = tid >> 1;
        const int db = (tid & 1) * 32;
        const float* qp = Qb + (size_t)qi * D_MODEL + db;
#pragma unroll
        for (int f = 0; f < 8; f++) {
            float4 v = *(const float4*)(qp + f * 4);
            v.x *= 0.125f; v.y *= 0.125f; v.z *= 0.125f; v.w *= 0.125f;
            unsigned h0, l0, h1, l1;
            split_pk(v.x, v.y, h0, l0);
            split_pk(v.z, v.w, h1, l1);
            const int c = (db + f * 4) >> 1;
            sm.q.hi[qi][c] = h0; sm.q.hi[qi][c + 1] = h1;
            sm.q.lo[qi][c] = l0; sm.q.lo[qi][c + 1] = l1;
        }
    }
    __syncthreads();

    // ---- extract Q fragments (persistent) ----
    unsigned qh[4][4], ql[4][4];
    {
        const int r = warp * 16 + (lane >> 2);
#pragma unroll
        for (int ks = 0; ks < 4; ks++) {
            const int c = ks * 8 + (lane & 3);
            qh[ks][0] = sm.q.hi[r][c];     qh[ks][1] = sm.q.hi[r + 8][c];
            qh[ks][2] = sm.q.hi[r][c + 4]; qh[ks][3] = sm.q.hi[r + 8][c + 4];
            ql[ks][0] = sm.q.lo[r][c];     ql[ks][1] = sm.q.lo[r + 8][c];
            ql[ks][2] = sm.q.lo[r][c + 4]; ql[ks][3] = sm.q.lo[r + 8][c + 4];
        }
    }

    float o[8][4];
#pragma unroll
    for (int jd = 0; jd < 8; jd++)
#pragma unroll
        for (int i = 0; i < 4; i++) o[jd][i] = 0.0f;
    float run_m1 = -1e30f, run_m2 = -1e30f, run_l1 = 0.0f, run_l2 = 0.0f;

    for (int kt = 0; kt < SEQ; kt += 64) {
        __syncthreads();   // previous tile consumed (also guards Q smem reuse)
        // ---- build K tile: pairs along d ----
#pragma unroll
        for (int pass = 0; pass < 8; pass++) {
            const int kv = pass * 8 + (tid >> 4);
            const int d4 = (tid & 15) * 4;
            float4 v = *(const float4*)(Kb + (size_t)(kt + kv) * D_MODEL + d4);
            unsigned h0, l0, h1, l1;
            split_pk(v.x, v.y, h0, l0);
            split_pk(v.z, v.w, h1, l1);
            const int c = d4 >> 1;
            sm.kv.khi[c][kv] = h0; sm.kv.khi[c + 1][kv] = h1;
            sm.kv.klo[c][kv] = l0; sm.kv.klo[c + 1][kv] = l1;
        }
        // ---- build V tile: pairs along kv (transposed packing) ----
#pragma unroll
        for (int pass = 0; pass < 4; pass++) {
            const int pr = pass * 8 + (tid >> 4);
            const int d4 = (tid & 15) * 4;
            const float* v0 = Vb + (size_t)(kt + 2 * pr) * D_MODEL + d4;
            float4 a = *(const float4*)v0;
            float4 bb = *(const float4*)(v0 + D_MODEL);
            unsigned hh, ll;
            split_pk(a.x, bb.x, hh, ll); sm.kv.vhi[pr][d4 + 0] = hh; sm.kv.vlo[pr][d4 + 0] = ll;
            split_pk(a.y, bb.y, hh, ll); sm.kv.vhi[pr][d4 + 1] = hh; sm.kv.vlo[pr][d4 + 1] = ll;
            split_pk(a.z, bb.z, hh, ll); sm.kv.vhi[pr][d4 + 2] = hh; sm.kv.vlo[pr][d4 + 2] = ll;
            split_pk(a.w, bb.w, hh, ll); sm.kv.vhi[pr][d4 + 3] = hh; sm.kv.vlo[pr][d4 + 3] = ll;
        }
        __syncthreads();

        // ---- S = Q K^T (split: 3 mmas) ----
        float s[8][4];
#pragma unroll
        for (int j = 0; j < 8; j++)
#pragma unroll
            for (int i = 0; i < 4; i++) s[j][i] = 0.0f;
#pragma unroll
        for (int ks = 0; ks < 4; ks++) {
            const int c = ks * 8 + (lane & 3);
#pragma unroll
            for (int j = 0; j < 8; j++) {
                const int n = j * 8 + (lane >> 2);
                const unsigned bh0 = sm.kv.khi[c][n], bh1 = sm.kv.khi[c + 4][n];
                const unsigned bl0 = sm.kv.klo[c][n], bl1 = sm.kv.klo[c + 4][n];
                mma16816(s[j], qh[ks][0], qh[ks][1], qh[ks][2], qh[ks][3], bh0, bh1);
                mma16816(s[j], qh[ks][0], qh[ks][1], qh[ks][2], qh[ks][3], bl0, bl1);
                mma16816(s[j], ql[ks][0], ql[ks][1], ql[ks][2], ql[ks][3], bh0, bh1);
            }
        }

        // ---- online softmax update ----
        float tm1 = -1e30f, tm2 = -1e30f;
#pragma unroll
        for (int j = 0; j < 8; j++) {
            tm1 = fmaxf(tm1, fmaxf(s[j][0], s[j][1]));
            tm2 = fmaxf(tm2, fmaxf(s[j][2], s[j][3]));
        }
        tm1 = fmaxf(tm1, __shfl_xor_sync(0xffffffffu, tm1, 1));
        tm1 = fmaxf(tm1, __shfl_xor_sync(0xffffffffu, tm1, 2));
        tm2 = fmaxf(tm2, __shfl_xor_sync(0xffffffffu, tm2, 1));
        tm2 = fmaxf(tm2, __shfl_xor_sync(0xffffffffu, tm2, 2));
        const float nm1 = fmaxf(run_m1, tm1);
        const float nm2 = fmaxf(run_m2, tm2);
        const float sc1 = __expf(run_m1 - nm1);
        const float sc2 = __expf(run_m2 - nm2);
        run_m1 = nm1; run_m2 = nm2;

        float ts1 = 0.0f, ts2 = 0.0f;
#pragma unroll
        for (int j = 0; j < 8; j++) {
            s[j][0] = __expf(s[j][0] - nm1);
            s[j][1] = __expf(s[j][1] - nm1);
            s[j][2] = __expf(s[j][2] - nm2);
            s[j][3] = __expf(s[j][3] - nm2);
            ts1 += s[j][0] + s[j][1];
            ts2 += s[j][2] + s[j][3];
        }
        ts1 += __shfl_xor_sync(0xffffffffu, ts1, 1);
        ts1 += __shfl_xor_sync(0xffffffffu, ts1, 2);
        ts2 += __shfl_xor_sync(0xffffffffu, ts2, 1);
        ts2 += __shfl_xor_sync(0xffffffffu, ts2, 2);
        run_l1 = run_l1 * sc1 + ts1;
        run_l2 = run_l2 * sc2 + ts2;

#pragma unroll
        for (int jd = 0; jd < 8; jd++) {
            o[jd][0] *= sc1; o[jd][1] *= sc1;
            o[jd][2] *= sc2; o[jd][3] *= sc2;
        }

        // ---- pack P fragments (C->A identity) ----
        unsigned ph[4][4], pl[4][4];
#pragma unroll
        for (int kp = 0; kp < 4; kp++) {
            split_pk(s[2 * kp][0],     s[2 * kp][1],     ph[kp][0], pl[kp][0]);
            split_pk(s[2 * kp][2],     s[2 * kp][3],     ph[kp][1], pl[kp][1]);
            split_pk(s[2 * kp + 1][0], s[2 * kp + 1][1], ph[kp][2], pl[kp][2]);
            split_pk(s[2 * kp + 1][2], s[2 * kp + 1][3], ph[kp][3], pl[kp][3]);
        }

        // ---- O += P V ----
#pragma unroll
        for (int kp = 0; kp < 4; kp++) {
            const int c = kp * 8 + (lane & 3);
#pragma unroll
            for (int jd = 0; jd < 8; jd++) {
                const int n = jd * 8 + (lane >> 2);
                const unsigned bh0 = sm.kv.vhi[c][n], bh1 = sm.kv.vhi[c + 4][n];
                const unsigned bl0 = sm.kv.vlo[c][n], bl1 = sm.kv.vlo[c + 4][n];
                mma16816(o[jd], ph[kp][0], ph[kp][1], ph[kp][2], ph[kp][3], bh0, bh1);
                mma16816(o[jd], ph[kp][0], ph[kp][1], ph[kp][2], ph[kp][3], bl0, bl1);
                mma16816(o[jd], pl[kp][0], pl[kp][1], pl[kp][2], pl[kp][3], bh0, bh1);
            }
        }
    }

    // ---- write O ----
    const float i1 = 1.0f / run_l1;
    const float i2 = 1.0f / run_l2;
    const int r1 = q0 + warp * 16 + (lane >> 2);
    float* Ob = O + ((size_t)(b * SEQ)) * D_MODEL + hoff;
#pragma unroll
    for (int jd = 0; jd < 8; jd++) {
        const int c = jd * 8 + 2 * (lane & 3);
        float2 w0; w0.x = o[jd][0] * i1; w0.y = o[jd][1] * i1;
        float2 w1; w1.x = o[jd][2] * i2; w1.y = o[jd][3] * i2;
        *(float2*)(Ob + (size_t)r1 * D_MODEL + c) = w0;
        *(float2*)(Ob + (size_t)(r1 + 8) * D_MODEL + c) = w1;
    }
}

// ---------------- LayerNorm over last dim (1024), one block per row ----------------
__global__ __launch_bounds__(256) void ln_kernel(
    const float* __restrict__ x, const float* __restrict__ w,
    const float* __restrict__ b, float* __restrict__ out, int ldo)
{
    const int row = blockIdx.x;
    const int tid = threadIdx.x;

    float4 v = ((const float4*)(x + (size_t)row * D_MODEL))[tid];
    float s  = v.x + v.y + v.z + v.w;
    float s2 = v.x * v.x + v.y * v.y + v.z * v.z + v.w * v.w;

#pragma unroll
    for (int off = 16; off > 0; off >>= 1) {
        s  += __shfl_xor_sync(0xffffffffu, s, off);
        s2 += __shfl_xor_sync(0xffffffffu, s2, off);
    }
    __shared__ float rs[8], rs2[8];
    __shared__ float smu, sinv;
    const int wid = tid >> 5;
    if ((tid & 31) == 0) { rs[wid] = s; rs2[wid] = s2; }
    __syncthreads();
    if (tid == 0) {
        float ts = 0.0f, ts2 = 0.0f;
#pragma unroll
        for (int i = 0; i < 8; i++) { ts += rs[i]; ts2 += rs2[i]; }
        float mu  = ts * (1.0f / D_MODEL);
        float var = ts2 * (1.0f / D_MODEL) - mu * mu;
        smu = mu;
        sinv = rsqrtf(var + 1e-5f);
    }
    __syncthreads();
    const float mu = smu, inv = sinv;

    float4 wv = ((const float4*)w)[tid];
    float4 bv = ((const float4*)b)[tid];
    float4 ov;
    ov.x = (v.x - mu) * inv * wv.x + bv.x;
    ov.y = (v.y - mu) * inv * wv.y + bv.y;
    ov.z = (v.z - mu) * inv * wv.z + bv.z;
    ov.w = (v.w - mu) * inv * wv.w + bv.w;
    ((float4*)(out + (size_t)row * ldo))[tid] = ov;
}

// ---------------- orchestration ----------------
extern "C" void kernel_launch(void* const* d_in, const int* in_sizes, int n_in,
                              void* d_out, int out_size)
{
    (void)in_sizes; (void)n_in; (void)out_size;

    const float* temporal = (const float*)d_in[0];
    const float* feature  = (const float*)d_in[1];
    const float* qt_w = (const float*)d_in[2];  const float* qt_b = (const float*)d_in[3];
    const float* kf_w = (const float*)d_in[4];  const float* kf_b = (const float*)d_in[5];
    const float* vf_w = (const float*)d_in[6];  const float* vf_b = (const float*)d_in[7];
    const float* qf_w = (const float*)d_in[8];  const float* qf_b = (const float*)d_in[9];
    const float* kt_w = (const float*)d_in[10]; const float* kt_b = (const float*)d_in[11];
    const float* vt_w = (const float*)d_in[12]; const float* vt_b = (const float*)d_in[13];
    const float* ot_w = (const float*)d_in[14]; const float* ot_b = (const float*)d_in[15];
    const float* of_w = (const float*)d_in[16]; const float* of_b = (const float*)d_in[17];
    const float* fus1_w = (const float*)d_in[18]; const float* fus1_b = (const float*)d_in[19];
    const float* fus2_w = (const float*)d_in[20]; const float* fus2_b = (const float*)d_in[21];
    const float* ln_fus_w = (const float*)d_in[22]; const float* ln_fus_b = (const float*)d_in[23];
    const float* ln_t_w = (const float*)d_in[24]; const float* ln_t_b = (const float*)d_in[25];
    const float* ln_f_w = (const float*)d_in[26]; const float* ln_f_b = (const float*)d_in[27];
    float* out = (float*)d_out;

    float *q, *k, *v, *attn, *t, *cat;
    cudaGetSymbolAddress((void**)&q,    g_q);
    cudaGetSymbolAddress((void**)&k,    g_k);
    cudaGetSymbolAddress((void**)&v,    g_v);
    cudaGetSymbolAddress((void**)&attn, g_attn);
    cudaGetSymbolAddress((void**)&t,    g_t);
    cudaGetSymbolAddress((void**)&cat,  g_cat);

    const dim3 ggrid(D_MODEL / 128, M_TOK / 128);  // (8, 64)
    const dim3 agrid(SEQ / 64, N_HEADS, BATCH);    // (32, 16, 4)

    // temporal -> feature cross attention
    tgemm_epi<0><<<ggrid, 256>>>(temporal, qt_w, qt_b, nullptr, q, M_TOK, D_MODEL, D_MODEL);
    tgemm_epi<0><<<ggrid, 256>>>(feature,  kf_w, kf_b, nullptr, k, M_TOK, D_MODEL, D_MODEL);
    tgemm_epi<0><<<ggrid, 256>>>(feature,  vf_w, vf_b, nullptr, v, M_TOK, D_MODEL, D_MODEL);
    attn_mma<<<agrid, 128>>>(q, k, v, attn);
    tgemm_epi<1><<<ggrid, 256>>>(attn, ot_w, ot_b, temporal, t, M_TOK, D_MODEL, D_MODEL);
    ln_kernel<<<M_TOK, 256>>>(t, ln_t_w, ln_t_b, cat, 2 * D_MODEL);

    // feature -> temporal cross attention
    tgemm_epi<0><<<ggrid, 256>>>(feature,  qf_w, qf_b, nullptr, q, M_TOK, D_MODEL, D_MODEL);
    tgemm_epi<0><<<ggrid, 256>>>(temporal, kt_w, kt_b, nullptr, k, M_TOK, D_MODEL, D_MODEL);
    tgemm_epi<0><<<ggrid, 256>>>(temporal, vt_w, vt_b, nullptr, v, M_TOK, D_MODEL, D_MODEL);
    attn_mma<<<agrid, 128>>>(q, k, v, attn);
    tgemm_epi<1><<<ggrid, 256>>>(attn, of_w, of_b, feature, t, M_TOK, D_MODEL, D_MODEL);
    ln_kernel<<<M_TOK, 256>>>(t, ln_f_w, ln_f_b, cat + D_MODEL, 2 * D_MODEL);

    // fusion MLP
    tgemm_epi<2><<<ggrid, 256>>>(cat, fus1_w, fus1_b, nullptr, q, M_TOK, D_MODEL, 2 * D_MODEL);
    tgemm_epi<0><<<ggrid, 256>>>(q,   fus2_w, fus2_b, nullptr, t, M_TOK, D_MODEL, D_MODEL);
    ln_kernel<<<M_TOK, 256>>>(t, ln_fus_w, ln_fus_b, out, D_MODEL);
}

// round 4
// speedup vs baseline: 3.3448x; 1.1850x over previous
#include <cuda_runtime.h>
#include <cuda_bf16.h>
#include <math.h>
#include <stdint.h>

#define D_MODEL 1024
#define N_HEADS 16
#define HEAD_DIM 64
#define BATCH 4
#define SEQ 2048
#define M_TOK (BATCH * SEQ) /* 8192 */

typedef __nv_bfloat16 bf16;

// ---------------- scratch (allocation-free: __device__ globals) ----------------
__device__ bf16 g_xt_hi[(size_t)M_TOK * D_MODEL], g_xt_lo[(size_t)M_TOK * D_MODEL];
__device__ bf16 g_xf_hi[(size_t)M_TOK * D_MODEL], g_xf_lo[(size_t)M_TOK * D_MODEL];
__device__ bf16 g_qh[(size_t)M_TOK * D_MODEL], g_ql[(size_t)M_TOK * D_MODEL];
__device__ bf16 g_kh[(size_t)M_TOK * D_MODEL], g_kl[(size_t)M_TOK * D_MODEL];
__device__ bf16 g_vh[(size_t)M_TOK * D_MODEL], g_vl[(size_t)M_TOK * D_MODEL];
__device__ bf16 g_ah[(size_t)M_TOK * D_MODEL], g_al[(size_t)M_TOK * D_MODEL];
__device__ bf16 g_cat_hi[(size_t)M_TOK * 2 * D_MODEL], g_cat_lo[(size_t)M_TOK * 2 * D_MODEL];
__device__ float g_t[(size_t)M_TOK * D_MODEL];
// transposed split weights pool: 9 x 1M + 1 x 2M = 11M elements
__device__ bf16 g_wp_hi[11u * 1024u * 1024u];
__device__ bf16 g_wp_lo[11u * 1024u * 1024u];

#define WOFF_QT 0u
#define WOFF_KF (1u * 1048576u)
#define WOFF_VF (2u * 1048576u)
#define WOFF_QF (3u * 1048576u)
#define WOFF_KT (4u * 1048576u)
#define WOFF_VT (5u * 1048576u)
#define WOFF_OT (6u * 1048576u)
#define WOFF_OF (7u * 1048576u)
#define WOFF_F2 (8u * 1048576u)
#define WOFF_F1 (9u * 1048576u)

// ---------------- helpers ----------------
__device__ __forceinline__ void split_pk(float a, float b, unsigned &hi, unsigned &lo) {
    bf16 ah = __float2bfloat16_rn(a);
    bf16 bh = __float2bfloat16_rn(b);
    hi = ((unsigned)__bfloat16_as_ushort(bh) << 16) | (unsigned)__bfloat16_as_ushort(ah);
    float ar = a - __bfloat162float(ah);
    float br = b - __bfloat162float(bh);
    lo = ((unsigned)__bfloat16_as_ushort(__float2bfloat16_rn(br)) << 16) |
         (unsigned)__bfloat16_as_ushort(__float2bfloat16_rn(ar));
}

__device__ __forceinline__ void mma16816(float* d, unsigned a0, unsigned a1,
                                         unsigned a2, unsigned a3,
                                         unsigned b0, unsigned b1) {
    asm volatile(
        "mma.sync.aligned.m16n8k16.row.col.f32.bf16.bf16.f32 "
        "{%0,%1,%2,%3},{%4,%5,%6,%7},{%8,%9},{%0,%1,%2,%3};"
        : "+f"(d[0]), "+f"(d[1]), "+f"(d[2]), "+f"(d[3])
        : "r"(a0), "r"(a1), "r"(a2), "r"(a3), "r"(b0), "r"(b1));
}

__device__ __forceinline__ unsigned saddr(const void* p) {
    return (unsigned)__cvta_generic_to_shared(p);
}
__device__ __forceinline__ void ldsm_x4(unsigned &r0, unsigned &r1, unsigned &r2,
                                        unsigned &r3, unsigned a) {
    asm volatile("ldmatrix.sync.aligned.m8n8.x4.shared.b16 {%0,%1,%2,%3},[%4];"
                 : "=r"(r0), "=r"(r1), "=r"(r2), "=r"(r3) : "r"(a));
}
__device__ __forceinline__ void ldsm_x4_t(unsigned &r0, unsigned &r1, unsigned &r2,
                                          unsigned &r3, unsigned a) {
    asm volatile("ldmatrix.sync.aligned.m8n8.x4.trans.shared.b16 {%0,%1,%2,%3},[%4];"
                 : "=r"(r0), "=r"(r1), "=r"(r2), "=r"(r3) : "r"(a));
}

// ---------------- converters ----------------
__global__ __launch_bounds__(256) void split_kernel(
    const float* __restrict__ in, bf16* __restrict__ hi, bf16* __restrict__ lo)
{
    const size_t i = (size_t)blockIdx.x * 256 + threadIdx.x;
    float4 v = ((const float4*)in)[i];
    unsigned h0, l0, h1, l1;
    split_pk(v.x, v.y, h0, l0);
    split_pk(v.z, v.w, h1, l1);
    uint2 hh; hh.x = h0; hh.y = h1;
    uint2 ll; ll.x = l0; ll.y = l1;
    ((uint2*)hi)[i] = hh;
    ((uint2*)lo)[i] = ll;
}

// W[K][N] fp32 -> T[N][K] split bf16
__global__ __launch_bounds__(256) void wconv(
    const float* __restrict__ W, bf16* __restrict__ Thi, bf16* __restrict__ Tlo,
    int K, int N)
{
    __shared__ float tile[32][33];
    const int tx = threadIdx.x, ty = threadIdx.y;
    const int n0 = blockIdx.x * 32;
    const int k0 = blockIdx.y * 32;
#pragma unroll
    for (int i = 0; i < 4; i++)
        tile[ty + 8 * i][tx] = W[(size_t)(k0 + ty + 8 * i) * N + n0 + tx];
    __syncthreads();
#pragma unroll
    for (int i = 0; i < 4; i++) {
        float v = tile[tx][ty + 8 * i];
        bf16 h = __float2bfloat16_rn(v);
        const size_t o = (size_t)(n0 + ty + 8 * i) * K + k0 + tx;
        Thi[o] = h;
        Tlo[o] = __float2bfloat16_rn(v - __bfloat162float(h));
    }
}

// ---------------- split-bf16 tensor-core GEMM, ldmatrix path ----------------
// C[M,N] = A[M,K] @ W[K,N] + bias. Operands pre-split; W pre-transposed [N][K].
// EPI: 0 bias->split out; 1 bias+resid->fp32; 2 bias+GELU->split out; 3 bias->fp32
template <int EPI>
__global__ __launch_bounds__(256, 2) void tgemm(
    const bf16* __restrict__ Ahi, const bf16* __restrict__ Alo,
    const bf16* __restrict__ Bhi, const bf16* __restrict__ Blo,
    const float* __restrict__ bias, const float* __restrict__ resid,
    float* __restrict__ Cf, bf16* __restrict__ Chi, bf16* __restrict__ Clo,
    int M, int N, int K)
{
    __shared__ __align__(16) bf16 sAhi[128][40], sAlo[128][40];
    __shared__ __align__(16) bf16 sBhi[128][40], sBlo[128][40];

    const int tid = threadIdx.x;
    const int lane = tid & 31;
    const int wid = tid >> 5;
    const int warpM = wid & 3;
    const int warpN = wid >> 2;
    const int brow = blockIdx.y * 128;
    const int bcol = blockIdx.x * 128;

    float acc[2][8][4];
#pragma unroll
    for (int mt = 0; mt < 2; mt++)
#pragma unroll
        for (int nt = 0; nt < 8; nt++)
#pragma unroll
            for (int i = 0; i < 4; i++) acc[mt][nt][i] = 0.0f;

    const int lrow = tid >> 1;
    const int lcb = (tid & 1) * 2;
    const bf16* gA_hi = Ahi + (size_t)(brow + lrow) * K;
    const bf16* gA_lo = Alo + (size_t)(brow + lrow) * K;
    const bf16* gB_hi = Bhi + (size_t)(bcol + lrow) * K;
    const bf16* gB_lo = Blo + (size_t)(bcol + lrow) * K;

    for (int k0 = 0; k0 < K; k0 += 32) {
        __syncthreads();
#pragma unroll
        for (int q = 0; q < 2; q++) {
            const int ch = lcb + q;
            *(uint4*)&sAhi[lrow][8 * ch] = *(const uint4*)(gA_hi + k0 + 8 * ch);
            *(uint4*)&sAlo[lrow][8 * ch] = *(const uint4*)(gA_lo + k0 + 8 * ch);
            *(uint4*)&sBhi[lrow][8 * ch] = *(const uint4*)(gB_hi + k0 + 8 * ch);
            *(uint4*)&sBlo[lrow][8 * ch] = *(const uint4*)(gB_lo + k0 + 8 * ch);
        }
        __syncthreads();

#pragma unroll
        for (int ks = 0; ks < 2; ks++) {
            unsigned ah[2][4], al[2][4];
#pragma unroll
            for (int mt = 0; mt < 2; mt++) {
                const int r = warpM * 32 + mt * 16 + (lane & 15);
                const int c = ks * 16 + ((lane & 16) >> 1);
                ldsm_x4(ah[mt][0], ah[mt][1], ah[mt][2], ah[mt][3], saddr(&sAhi[r][c]));
                ldsm_x4(al[mt][0], al[mt][1], al[mt][2], al[mt][3], saddr(&sAlo[r][c]));
            }
#pragma unroll
            for (int ntp = 0; ntp < 4; ntp++) {
                const int r = warpN * 64 + ntp * 16 + (lane & 7) + ((lane & 16) >> 1);
                const int c = ks * 16 + (lane & 8);
                unsigned bh[4], bl[4];
                ldsm_x4(bh[0], bh[1], bh[2], bh[3], saddr(&sBhi[r][c]));
                ldsm_x4(bl[0], bl[1], bl[2], bl[3], saddr(&sBlo[r][c]));
#pragma unroll
                for (int half = 0; half < 2; half++) {
                    const int nt = 2 * ntp + half;
#pragma unroll
                    for (int mt = 0; mt < 2; mt++) {
                        mma16816(acc[mt][nt], ah[mt][0], ah[mt][1], ah[mt][2], ah[mt][3],
                                 bh[2 * half], bh[2 * half + 1]);
                        mma16816(acc[mt][nt], ah[mt][0], ah[mt][1], ah[mt][2], ah[mt][3],
                                 bl[2 * half], bl[2 * half + 1]);
                        mma16816(acc[mt][nt], al[mt][0], al[mt][1], al[mt][2], al[mt][3],
                                 bh[2 * half], bh[2 * half + 1]);
                    }
                }
            }
        }
    }

    // ---- epilogue ----
#pragma unroll
    for (int mt = 0; mt < 2; mt++) {
#pragma unroll
        for (int half = 0; half < 2; half++) {
            const int r = brow + warpM * 32 + mt * 16 + (lane >> 2) + half * 8;
#pragma unroll
            for (int nt = 0; nt < 8; nt++) {
                const int c = bcol + warpN * 64 + nt * 8 + 2 * (lane & 3);
                float2 bv = *(const float2*)(bias + c);
                float x = acc[mt][nt][half * 2 + 0] + bv.x;
                float y = acc[mt][nt][half * 2 + 1] + bv.y;
                if (EPI == 1) {
                    float2 rv = *(const float2*)(resid + (size_t)r * N + c);
                    x += rv.x; y += rv.y;
                }
                if (EPI == 2) {
                    x = 0.5f * x * (1.0f + erff(x * 0.7071067811865475f));
                    y = 0.5f * y * (1.0f + erff(y * 0.7071067811865475f));
                }
                if (EPI == 1 || EPI == 3) {
                    float2 o2; o2.x = x; o2.y = y;
                    *(float2*)(Cf + (size_t)r * N + c) = o2;
                } else {
                    unsigned h, l;
                    split_pk(x, y, h, l);
                    *(unsigned*)(Chi + (size_t)r * N + c) = h;
                    *(unsigned*)(Clo + (size_t)r * N + c) = l;
                }
            }
        }
    }
}

// ---------------- flash attention: pre-split bf16 in, ldmatrix, online softmax ----
__global__ __launch_bounds__(128) void attn_mma(
    const bf16* __restrict__ Qh, const bf16* __restrict__ Ql,
    const bf16* __restrict__ Kh, const bf16* __restrict__ Kl,
    const bf16* __restrict__ Vh, const bf16* __restrict__ Vl,
    bf16* __restrict__ Ohi, bf16* __restrict__ Olo)
{
    __shared__ __align__(16) union {
        struct { bf16 hi[64][72], lo[64][72]; } q;
        struct { bf16 kh[64][72], kl[64][72], vh[64][72], vl[64][72]; } kv;
    } sm;

    const int tid = threadIdx.x;
    const int lane = tid & 31;
    const int warp = tid >> 5;
    const int b = blockIdx.z;
    const int h = blockIdx.y;
    const int q0 = blockIdx.x * 64;
    const int hoff = h * HEAD_DIM;

    const bf16* Qbh = Qh + (size_t)(b * SEQ + q0) * D_MODEL + hoff;
    const bf16* Qbl = Ql + (size_t)(b * SEQ + q0) * D_MODEL + hoff;
    const bf16* Kbh = Kh + (size_t)(b * SEQ) * D_MODEL + hoff;
    const bf16* Kbl = Kl + (size_t)(b * SEQ) * D_MODEL + hoff;
    const bf16* Vbh = Vh + (size_t)(b * SEQ) * D_MODEL + hoff;
    const bf16* Vbl = Vl + (size_t)(b * SEQ) * D_MODEL + hoff;

    // ---- stage Q, extract fragments ----
#pragma unroll
    for (int i = 0; i < 4; i++) {
        const int cid = i * 128 + tid;       // 512 chunks per array
        const int row = cid >> 3;
        const int ch = cid & 7;
        *(uint4*)&sm.q.hi[row][8 * ch] = *(const uint4*)(Qbh + (size_t)row * D_MODEL + 8 * ch);
        *(uint4*)&sm.q.lo[row][8 * ch] = *(const uint4*)(Qbl + (size_t)row * D_MODEL + 8 * ch);
    }
    __syncthreads();

    unsigned qh[4][4], ql[4][4];
    {
        const int r = warp * 16 + (lane & 15);
#pragma unroll
        for (int ks = 0; ks < 4; ks++) {
            const int c = ks * 16 + ((lane & 16) >> 1);
            ldsm_x4(qh[ks][0], qh[ks][1], qh[ks][2], qh[ks][3], saddr(&sm.q.hi[r][c]));
            ldsm_x4(ql[ks][0], ql[ks][1], ql[ks][2], ql[ks][3], saddr(&sm.q.lo[r][c]));
        }
    }

    float o[8][4];
#pragma unroll
    for (int jd = 0; jd < 8; jd++)
#pragma unroll
        for (int i = 0; i < 4; i++) o[jd][i] = 0.0f;
    float run_m1 = -1e30f, run_m2 = -1e30f, run_l1 = 0.0f, run_l2 = 0.0f;

    for (int kt = 0; kt < SEQ; kt += 64) {
        __syncthreads();
#pragma unroll
        for (int i = 0; i < 4; i++) {
            const int cid = i * 128 + tid;
            const int row = cid >> 3;
            const int ch = cid & 7;
            const size_t go = (size_t)(kt + row) * D_MODEL + 8 * ch;
            *(uint4*)&sm.kv.kh[row][8 * ch] = *(const uint4*)(Kbh + go);
            *(uint4*)&sm.kv.kl[row][8 * ch] = *(const uint4*)(Kbl + go);
            *(uint4*)&sm.kv.vh[row][8 * ch] = *(const uint4*)(Vbh + go);
            *(uint4*)&sm.kv.vl[row][8 * ch] = *(const uint4*)(Vbl + go);
        }
        __syncthreads();

        // ---- S = Q K^T ----
        float s[8][4];
#pragma unroll
        for (int j = 0; j < 8; j++)
#pragma unroll
            for (int i = 0; i < 4; i++) s[j][i] = 0.0f;
#pragma unroll
        for (int ks = 0; ks < 4; ks++) {
#pragma unroll
            for (int ntp = 0; ntp < 4; ntp++) {
                const int r = ntp * 16 + (lane & 7) + ((lane & 16) >> 1);
                const int c = ks * 16 + (lane & 8);
                unsigned bh[4], bl[4];
                ldsm_x4(bh[0], bh[1], bh[2], bh[3], saddr(&sm.kv.kh[r][c]));
                ldsm_x4(bl[0], bl[1], bl[2], bl[3], saddr(&sm.kv.kl[r][c]));
#pragma unroll
                for (int half = 0; half < 2; half++) {
                    const int j = 2 * ntp + half;
                    mma16816(s[j], qh[ks][0], qh[ks][1], qh[ks][2], qh[ks][3],
                             bh[2 * half], bh[2 * half + 1]);
                    mma16816(s[j], qh[ks][0], qh[ks][1], qh[ks][2], qh[ks][3],
                             bl[2 * half], bl[2 * half + 1]);
                    mma16816(s[j], ql[ks][0], ql[ks][1], ql[ks][2], ql[ks][3],
                             bh[2 * half], bh[2 * half + 1]);
                }
            }
        }
#pragma unroll
        for (int j = 0; j < 8; j++)
#pragma unroll
            for (int i = 0; i < 4; i++) s[j][i] *= 0.125f;   // 1/sqrt(64)

        // ---- online softmax ----
        float tm1 = -1e30f, tm2 = -1e30f;
#pragma unroll
        for (int j = 0; j < 8; j++) {
            tm1 = fmaxf(tm1, fmaxf(s[j][0], s[j][1]));
            tm2 = fmaxf(tm2, fmaxf(s[j][2], s[j][3]));
        }
        tm1 = fmaxf(tm1, __shfl_xor_sync(0xffffffffu, tm1, 1));
        tm1 = fmaxf(tm1, __shfl_xor_sync(0xffffffffu, tm1, 2));
        tm2 = fmaxf(tm2, __shfl_xor_sync(0xffffffffu, tm2, 1));
        tm2 = fmaxf(tm2, __shfl_xor_sync(0xffffffffu, tm2, 2));
        const float nm1 = fmaxf(run_m1, tm1);
        const float nm2 = fmaxf(run_m2, tm2);
        const float sc1 = __expf(run_m1 - nm1);
        const float sc2 = __expf(run_m2 - nm2);
        run_m1 = nm1; run_m2 = nm2;

        float ts1 = 0.0f, ts2 = 0.0f;
#pragma unroll
        for (int j = 0; j < 8; j++) {
            s[j][0] = __expf(s[j][0] - nm1);
            s[j][1] = __expf(s[j][1] - nm1);
            s[j][2] = __expf(s[j][2] - nm2);
            s[j][3] = __expf(s[j][3] - nm2);
            ts1 += s[j][0] + s[j][1];
            ts2 += s[j][2] + s[j][3];
        }
        ts1 += __shfl_xor_sync(0xffffffffu, ts1, 1);
        ts1 += __shfl_xor_sync(0xffffffffu, ts1, 2);
        ts2 += __shfl_xor_sync(0xffffffffu, ts2, 1);
        ts2 += __shfl_xor_sync(0xffffffffu, ts2, 2);
        run_l1 = run_l1 * sc1 + ts1;
        run_l2 = run_l2 * sc2 + ts2;
#pragma unroll
        for (int jd = 0; jd < 8; jd++) {
            o[jd][0] *= sc1; o[jd][1] *= sc1;
            o[jd][2] *= sc2; o[jd][3] *= sc2;
        }

        // ---- O += P V ----
#pragma unroll
        for (int kp = 0; kp < 4; kp++) {
            unsigned ph[4], pl[4];
            split_pk(s[2 * kp][0],     s[2 * kp][1],     ph[0], pl[0]);
            split_pk(s[2 * kp][2],     s[2 * kp][3],     ph[1], pl[1]);
            split_pk(s[2 * kp + 1][0], s[2 * kp + 1][1], ph[2], pl[2]);
            split_pk(s[2 * kp + 1][2], s[2 * kp + 1][3], ph[3], pl[3]);
#pragma unroll
            for (int dntp = 0; dntp < 4; dntp++) {
                const int r = kp * 16 + (lane & 15);
                const int c = dntp * 16 + ((lane & 16) >> 1);
                unsigned vh[4], vl[4];
                ldsm_x4_t(vh[0], vh[1], vh[2], vh[3], saddr(&sm.kv.vh[r][c]));
                ldsm_x4_t(vl[0], vl[1], vl[2], vl[3], saddr(&sm.kv.vl[r][c]));
#pragma unroll
                for (int half = 0; half < 2; half++) {
                    const int jd = 2 * dntp + half;
                    mma16816(o[jd], ph[0], ph[1], ph[2], ph[3], vh[2 * half], vh[2 * half + 1]);
                    mma16816(o[jd], ph[0], ph[1], ph[2], ph[3], vl[2 * half], vl[2 * half + 1]);
                    mma16816(o[jd], pl[0], pl[1], pl[2], pl[3], vh[2 * half], vh[2 * half + 1]);
                }
            }
        }
    }

    // ---- write O as split bf16 ----
    const float i1 = 1.0f / run_l1;
    const float i2 = 1.0f / run_l2;
    const int r1 = b * SEQ + q0 + warp * 16 + (lane >> 2);
#pragma unroll
    for (int jd = 0; jd < 8; jd++) {
        const int c = hoff + jd * 8 + 2 * (lane & 3);
        unsigned h0, l0, h1, l1;
        split_pk(o[jd][0] * i1, o[jd][1] * i1, h0, l0);
        split_pk(o[jd][2] * i2, o[jd][3] * i2, h1, l1);
        *(unsigned*)(Ohi + (size_t)r1 * D_MODEL + c) = h0;
        *(unsigned*)(Olo + (size_t)r1 * D_MODEL + c) = l0;
        *(unsigned*)(Ohi + (size_t)(r1 + 8) * D_MODEL + c) = h1;
        *(unsigned*)(Olo + (size_t)(r1 + 8) * D_MODEL + c) = l1;
    }
}

// ---------------- LayerNorm: OUT=0 fp32 out, OUT=1 split-bf16 out ----------------
template <int OUT>
__global__ __launch_bounds__(256) void ln_kernel(
    const float* __restrict__ x, const float* __restrict__ w,
    const float* __restrict__ b, float* __restrict__ outf,
    bf16* __restrict__ outhi, bf16* __restrict__ outlo, int ldo)
{
    const int row = blockIdx.x;
    const int tid = threadIdx.x;

    float4 v = ((const float4*)(x + (size_t)row * D_MODEL))[tid];
    float s  = v.x + v.y + v.z + v.w;
    float s2 = v.x * v.x + v.y * v.y + v.z * v.z + v.w * v.w;
#pragma unroll
    for (int off = 16; off > 0; off >>= 1) {
        s  += __shfl_xor_sync(0xffffffffu, s, off);
        s2 += __shfl_xor_sync(0xffffffffu, s2, off);
    }
    __shared__ float rs[8], rs2[8];
    __shared__ float smu, sinv;
    const int wid = tid >> 5;
    if ((tid & 31) == 0) { rs[wid] = s; rs2[wid] = s2; }
    __syncthreads();
    if (tid == 0) {
        float ts = 0.0f, ts2 = 0.0f;
#pragma unroll
        for (int i = 0; i < 8; i++) { ts += rs[i]; ts2 += rs2[i]; }
        float mu  = ts * (1.0f / D_MODEL);
        float var = ts2 * (1.0f / D_MODEL) - mu * mu;
        smu = mu;
        sinv = rsqrtf(var + 1e-5f);
    }
    __syncthreads();
    const float mu = smu, inv = sinv;

    float4 wv = ((const float4*)w)[tid];
    float4 bv = ((const float4*)b)[tid];
    float4 ov;
    ov.x = (v.x - mu) * inv * wv.x + bv.x;
    ov.y = (v.y - mu) * inv * wv.y + bv.y;
    ov.z = (v.z - mu) * inv * wv.z + bv.z;
    ov.w = (v.w - mu) * inv * wv.w + bv.w;
    if (OUT == 0) {
        ((float4*)(outf + (size_t)row * ldo))[tid] = ov;
    } else {
        unsigned h0, l0, h1, l1;
        split_pk(ov.x, ov.y, h0, l0);
        split_pk(ov.z, ov.w, h1, l1);
        unsigned* ph = (unsigned*)(outhi + (size_t)row * ldo + 4 * tid);
        unsigned* pl = (unsigned*)(outlo + (size_t)row * ldo + 4 * tid);
        ph[0] = h0; ph[1] = h1;
        pl[0] = l0; pl[1] = l1;
    }
}

// ---------------- orchestration ----------------
extern "C" void kernel_launch(void* const* d_in, const int* in_sizes, int n_in,
                              void* d_out, int out_size)
{
    (void)in_sizes; (void)n_in; (void)out_size;

    const float* temporal = (const float*)d_in[0];
    const float* feature  = (const float*)d_in[1];
    const float* qt_w = (const float*)d_in[2];  const float* qt_b = (const float*)d_in[3];
    const float* kf_w = (const float*)d_in[4];  const float* kf_b = (const float*)d_in[5];
    const float* vf_w = (const float*)d_in[6];  const float* vf_b = (const float*)d_in[7];
    const float* qf_w = (const float*)d_in[8];  const float* qf_b = (const float*)d_in[9];
    const float* kt_w = (const float*)d_in[10]; const float* kt_b = (const float*)d_in[11];
    const float* vt_w = (const float*)d_in[12]; const float* vt_b = (const float*)d_in[13];
    const float* ot_w = (const float*)d_in[14]; const float* ot_b = (const float*)d_in[15];
    const float* of_w = (const float*)d_in[16]; const float* of_b = (const float*)d_in[17];
    const float* fus1_w = (const float*)d_in[18]; const float* fus1_b = (const float*)d_in[19];
    const float* fus2_w = (const float*)d_in[20]; const float* fus2_b = (const float*)d_in[21];
    const float* ln_fus_w = (const float*)d_in[22]; const float* ln_fus_b = (const float*)d_in[23];
    const float* ln_t_w = (const float*)d_in[24]; const float* ln_t_b = (const float*)d_in[25];
    const float* ln_f_w = (const float*)d_in[26]; const float* ln_f_b = (const float*)d_in[27];
    float* out = (float*)d_out;

    bf16 *xt_hi, *xt_lo, *xf_hi, *xf_lo, *qh, *ql, *kh, *kl, *vh, *vl, *ah, *al;
    bf16 *cat_hi, *cat_lo, *wp_hi, *wp_lo;
    float *t;
    cudaGetSymbolAddress((void**)&xt_hi, g_xt_hi); cudaGetSymbolAddress((void**)&xt_lo, g_xt_lo);
    cudaGetSymbolAddress((void**)&xf_hi, g_xf_hi); cudaGetSymbolAddress((void**)&xf_lo, g_xf_lo);
    cudaGetSymbolAddress((void**)&qh, g_qh); cudaGetSymbolAddress((void**)&ql, g_ql);
    cudaGetSymbolAddress((void**)&kh, g_kh); cudaGetSymbolAddress((void**)&kl, g_kl);
    cudaGetSymbolAddress((void**)&vh, g_vh); cudaGetSymbolAddress((void**)&vl, g_vl);
    cudaGetSymbolAddress((void**)&ah, g_ah); cudaGetSymbolAddress((void**)&al, g_al);
    cudaGetSymbolAddress((void**)&cat_hi, g_cat_hi); cudaGetSymbolAddress((void**)&cat_lo, g_cat_lo);
    cudaGetSymbolAddress((void**)&wp_hi, g_wp_hi); cudaGetSymbolAddress((void**)&wp_lo, g_wp_lo);
    cudaGetSymbolAddress((void**)&t, g_t);

    const int nblk = (M_TOK * D_MODEL) / 1024;  // split_kernel blocks
    const dim3 tgrid(1024 / 32, 1024 / 32);
    const dim3 tgrid1(1024 / 32, 2048 / 32);
    const dim3 tblk(32, 8);
    const dim3 ggrid(D_MODEL / 128, M_TOK / 128);  // (8, 64)
    const dim3 agrid(SEQ / 64, N_HEADS, BATCH);    // (32, 16, 4)

    // ---- conversions ----
    split_kernel<<<nblk, 256>>>(temporal, xt_hi, xt_lo);
    split_kernel<<<nblk, 256>>>(feature,  xf_hi, xf_lo);
    wconv<<<tgrid, tblk>>>(qt_w, wp_hi + WOFF_QT, wp_lo + WOFF_QT, 1024, 1024);
    wconv<<<tgrid, tblk>>>(kf_w, wp_hi + WOFF_KF, wp_lo + WOFF_KF, 1024, 1024);
    wconv<<<tgrid, tblk>>>(vf_w, wp_hi + WOFF_VF, wp_lo + WOFF_VF, 1024, 1024);
    wconv<<<tgrid, tblk>>>(qf_w, wp_hi + WOFF_QF, wp_lo + WOFF_QF, 1024, 1024);
    wconv<<<tgrid, tblk>>>(kt_w, wp_hi + WOFF_KT, wp_lo + WOFF_KT, 1024, 1024);
    wconv<<<tgrid, tblk>>>(vt_w, wp_hi + WOFF_VT, wp_lo + WOFF_VT, 1024, 1024);
    wconv<<<tgrid, tblk>>>(ot_w, wp_hi + WOFF_OT, wp_lo + WOFF_OT, 1024, 1024);
    wconv<<<tgrid, tblk>>>(of_w, wp_hi + WOFF_OF, wp_lo + WOFF_OF, 1024, 1024);
    wconv<<<tgrid, tblk>>>(fus2_w, wp_hi + WOFF_F2, wp_lo + WOFF_F2, 1024, 1024);
    wconv<<<tgrid1, tblk>>>(fus1_w, wp_hi + WOFF_F1, wp_lo + WOFF_F1, 2048, 1024);

    // ---- temporal -> feature cross attention ----
    tgemm<0><<<ggrid, 256>>>(xt_hi, xt_lo, wp_hi + WOFF_QT, wp_lo + WOFF_QT, qt_b, nullptr,
                             nullptr, qh, ql, M_TOK, D_MODEL, D_MODEL);
    tgemm<0><<<ggrid, 256>>>(xf_hi, xf_lo, wp_hi + WOFF_KF, wp_lo + WOFF_KF, kf_b, nullptr,
                             nullptr, kh, kl, M_TOK, D_MODEL, D_MODEL);
    tgemm<0><<<ggrid, 256>>>(xf_hi, xf_lo, wp_hi + WOFF_VF, wp_lo + WOFF_VF, vf_b, nullptr,
                             nullptr, vh, vl, M_TOK, D_MODEL, D_MODEL);
    attn_mma<<<agrid, 128>>>(qh, ql, kh, kl, vh, vl, ah, al);
    tgemm<1><<<ggrid, 256>>>(ah, al, wp_hi + WOFF_OT, wp_lo + WOFF_OT, ot_b, temporal,
                             t, nullptr, nullptr, M_TOK, D_MODEL, D_MODEL);
    ln_kernel<1><<<M_TOK, 256>>>(t, ln_t_w, ln_t_b, nullptr, cat_hi, cat_lo, 2 * D_MODEL);

    // ---- feature -> temporal cross attention ----
    tgemm<0><<<ggrid, 256>>>(xf_hi, xf_lo, wp_hi + WOFF_QF, wp_lo + WOFF_QF, qf_b, nullptr,
                             nullptr, qh, ql, M_TOK, D_MODEL, D_MODEL);
    tgemm<0><<<ggrid, 256>>>(xt_hi, xt_lo, wp_hi + WOFF_KT, wp_lo + WOFF_KT, kt_b, nullptr,
                             nullptr, kh, kl, M_TOK, D_MODEL, D_MODEL);
    tgemm<0><<<ggrid, 256>>>(xt_hi, xt_lo, wp_hi + WOFF_VT, wp_lo + WOFF_VT, vt_b, nullptr,
                             nullptr, vh, vl, M_TOK, D_MODEL, D_MODEL);
    attn_mma<<<agrid, 128>>>(qh, ql, kh, kl, vh, vl, ah, al);
    tgemm<1><<<ggrid, 256>>>(ah, al, wp_hi + WOFF_OF, wp_lo + WOFF_OF, of_b, feature,
                             t, nullptr, nullptr, M_TOK, D_MODEL, D_MODEL);
    ln_kernel<1><<<M_TOK, 256>>>(t, ln_f_w, ln_f_b, nullptr, cat_hi + D_MODEL, cat_lo + D_MODEL,
                                 2 * D_MODEL);

    // ---- fusion MLP ----
    tgemm<2><<<ggrid, 256>>>(cat_hi, cat_lo, wp_hi + WOFF_F1, wp_lo + WOFF_F1, fus1_b, nullptr,
                             nullptr, qh, ql, M_TOK, D_MODEL, 2 * D_MODEL);
    tgemm<3><<<ggrid, 256>>>(qh, ql, wp_hi + WOFF_F2, wp_lo + WOFF_F2, fus2_b, nullptr,
                             t, nullptr, nullptr, M_TOK, D_MODEL, D_MODEL);
    ln_kernel<0><<<M_TOK, 256>>>(t, ln_fus_w, ln_fus_b, out, nullptr, nullptr, D_MODEL);
}

// round 6
// speedup vs baseline: 3.8156x; 1.1407x over previous
#include <cuda_runtime.h>
#include <cuda_bf16.h>
#include <math.h>
#include <stdint.h>

#define D_MODEL 1024
#define N_HEADS 16
#define HEAD_DIM 64
#define BATCH 4
#define SEQ 2048
#define M_TOK (BATCH * SEQ) /* 8192 */

typedef __nv_bfloat16 bf16;

// ---------------- scratch (allocation-free: __device__ globals) ----------------
__device__ bf16 g_xt_hi[(size_t)M_TOK * D_MODEL], g_xt_lo[(size_t)M_TOK * D_MODEL];
__device__ bf16 g_xf_hi[(size_t)M_TOK * D_MODEL], g_xf_lo[(size_t)M_TOK * D_MODEL];
__device__ bf16 g_qh[(size_t)M_TOK * D_MODEL], g_ql[(size_t)M_TOK * D_MODEL];
__device__ bf16 g_kh[(size_t)M_TOK * D_MODEL], g_kl[(size_t)M_TOK * D_MODEL];
__device__ bf16 g_vh[(size_t)M_TOK * D_MODEL], g_vl[(size_t)M_TOK * D_MODEL];
__device__ bf16 g_ah[(size_t)M_TOK * D_MODEL], g_al[(size_t)M_TOK * D_MODEL];
__device__ bf16 g_cat_hi[(size_t)M_TOK * 2 * D_MODEL], g_cat_lo[(size_t)M_TOK * 2 * D_MODEL];
__device__ float g_t[(size_t)M_TOK * D_MODEL];
__device__ bf16 g_wp_hi[11u * 1024u * 1024u];
__device__ bf16 g_wp_lo[11u * 1024u * 1024u];

#define WOFF_QT 0u
#define WOFF_KF (1u * 1048576u)
#define WOFF_VF (2u * 1048576u)
#define WOFF_QF (3u * 1048576u)
#define WOFF_KT (4u * 1048576u)
#define WOFF_VT (5u * 1048576u)
#define WOFF_OT (6u * 1048576u)
#define WOFF_OF (7u * 1048576u)
#define WOFF_F2 (8u * 1048576u)
#define WOFF_F1 (9u * 1048576u)

// ---------------- helpers ----------------
__device__ __forceinline__ void split_pk(float a, float b, unsigned &hi, unsigned &lo) {
    bf16 ah = __float2bfloat16_rn(a);
    bf16 bh = __float2bfloat16_rn(b);
    hi = ((unsigned)__bfloat16_as_ushort(bh) << 16) | (unsigned)__bfloat16_as_ushort(ah);
    float ar = a - __bfloat162float(ah);
    float br = b - __bfloat162float(bh);
    lo = ((unsigned)__bfloat16_as_ushort(__float2bfloat16_rn(br)) << 16) |
         (unsigned)__bfloat16_as_ushort(__float2bfloat16_rn(ar));
}

__device__ __forceinline__ void mma16816(float* d, unsigned a0, unsigned a1,
                                         unsigned a2, unsigned a3,
                                         unsigned b0, unsigned b1) {
    asm volatile(
        "mma.sync.aligned.m16n8k16.row.col.f32.bf16.bf16.f32 "
        "{%0,%1,%2,%3},{%4,%5,%6,%7},{%8,%9},{%0,%1,%2,%3};"
        : "+f"(d[0]), "+f"(d[1]), "+f"(d[2]), "+f"(d[3])
        : "r"(a0), "r"(a1), "r"(a2), "r"(a3), "r"(b0), "r"(b1));
}

__device__ __forceinline__ unsigned saddr(const void* p) {
    return (unsigned)__cvta_generic_to_shared(p);
}
__device__ __forceinline__ void ldsm_x4(unsigned &r0, unsigned &r1, unsigned &r2,
                                        unsigned &r3, unsigned a) {
    asm volatile("ldmatrix.sync.aligned.m8n8.x4.shared.b16 {%0,%1,%2,%3},[%4];"
                 : "=r"(r0), "=r"(r1), "=r"(r2), "=r"(r3) : "r"(a));
}
__device__ __forceinline__ void ldsm_x4_t(unsigned &r0, unsigned &r1, unsigned &r2,
                                          unsigned &r3, unsigned a) {
    asm volatile("ldmatrix.sync.aligned.m8n8.x4.trans.shared.b16 {%0,%1,%2,%3},[%4];"
                 : "=r"(r0), "=r"(r1), "=r"(r2), "=r"(r3) : "r"(a));
}
__device__ __forceinline__ void cp16(unsigned dst, const void* src) {
    asm volatile("cp.async.cg.shared.global [%0], [%1], 16;" :: "r"(dst), "l"(src));
}
__device__ __forceinline__ void cp_commit() {
    asm volatile("cp.async.commit_group;");
}
__device__ __forceinline__ void cp_wait1() {
    asm volatile("cp.async.wait_group 1;" ::: "memory");
}

// ---------------- converters ----------------
__global__ __launch_bounds__(256) void split_kernel(
    const float* __restrict__ in, bf16* __restrict__ hi, bf16* __restrict__ lo)
{
    const size_t i = (size_t)blockIdx.x * 256 + threadIdx.x;
    float4 v = ((const float4*)in)[i];
    unsigned h0, l0, h1, l1;
    split_pk(v.x, v.y, h0, l0);
    split_pk(v.z, v.w, h1, l1);
    uint2 hh; hh.x = h0; hh.y = h1;
    uint2 ll; ll.x = l0; ll.y = l1;
    ((uint2*)hi)[i] = hh;
    ((uint2*)lo)[i] = ll;
}

// W[K][N] fp32 -> T[N][K] split bf16
__global__ __launch_bounds__(256) void wconv(
    const float* __restrict__ W, bf16* __restrict__ Thi, bf16* __restrict__ Tlo,
    int K, int N)
{
    __shared__ float tile[32][33];
    const int tx = threadIdx.x, ty = threadIdx.y;
    const int n0 = blockIdx.x * 32;
    const int k0 = blockIdx.y * 32;
#pragma unroll
    for (int i = 0; i < 4; i++)
        tile[ty + 8 * i][tx] = W[(size_t)(k0 + ty + 8 * i) * N + n0 + tx];
    __syncthreads();
#pragma unroll
    for (int i = 0; i < 4; i++) {
        float v = tile[tx][ty + 8 * i];
        bf16 h = __float2bfloat16_rn(v);
        const size_t o = (size_t)(n0 + ty + 8 * i) * K + k0 + tx;
        Thi[o] = h;
        Tlo[o] = __float2bfloat16_rn(v - __bfloat162float(v != v ? h : h));
        Tlo[o] = __float2bfloat16_rn(v - __bfloat162float(h));
    }
}

// ---------------- split-bf16 mma.sync GEMM, cp.async 2-stage pipeline ----------------
// C[M,N] = A[M,K] @ W[K,N] + bias. A pre-split [M][K]; W pre-split transposed [N][K].
// EPI: 0 bias->split out; 1 bias+resid->fp32; 2 bias+GELU->split out; 3 bias->fp32
// Stage layout (bf16, 128 rows x 40 cols padded): Ahi | Alo | Bhi | Blo, 10240 B each.
#define TG_STAGE 40960
#define TG_SMEM (2 * TG_STAGE)
template <int EPI>
__global__ __launch_bounds__(256, 2) void tgemm(
    const bf16* __restrict__ Ahi, const bf16* __restrict__ Alo,
    const bf16* __restrict__ Bhi, const bf16* __restrict__ Blo,
    const float* __restrict__ bias, const float* __restrict__ resid,
    float* __restrict__ Cf, bf16* __restrict__ Chi, bf16* __restrict__ Clo,
    int M, int N, int K)
{
    extern __shared__ __align__(16) char smem_raw[];
    const int tid = threadIdx.x;
    const int lane = tid & 31;
    const int wid = tid >> 5;
    const int warpM = wid & 3;
    const int warpN = wid >> 2;
    const int brow = blockIdx.y * 128;
    const int bcol = blockIdx.x * 128;

    float acc[2][8][4];
#pragma unroll
    for (int mt = 0; mt < 2; mt++)
#pragma unroll
        for (int nt = 0; nt < 8; nt++)
#pragma unroll
            for (int i = 0; i < 4; i++) acc[mt][nt][i] = 0.0f;

    const unsigned sb = saddr(smem_raw);
    const int nchunk = K >> 5;   // BK = 32

    // loader: per array 512 16B-chunks (128 rows x 4), 2 per thread
    const int r0 = (tid * 2) >> 3;        // rows: cid = 2*tid + q, r = cid>>2
    // (computed inline below)

    // ---- stage loader ----
    auto load_stage = [&](int c) {
        const int s = c & 1;
        const unsigned stg = sb + s * TG_STAGE;
        const int k0 = c * 32;
#pragma unroll
        for (int q = 0; q < 2; q++) {
            const int cid = tid * 2 + q;          // 0..511
            const int r = cid >> 2;
            const int cb = cid & 3;
            const unsigned so = (unsigned)(r * 80 + cb * 16);
            const size_t goA = (size_t)(brow + r) * K + k0 + cb * 8;
            const size_t goB = (size_t)(bcol + r) * K + k0 + cb * 8;
            cp16(stg + so,          Ahi + goA);
            cp16(stg + 10240 + so,  Alo + goA);
            cp16(stg + 20480 + so,  Bhi + goB);
            cp16(stg + 30720 + so,  Blo + goB);
        }
    };

    load_stage(0); cp_commit();
    load_stage(1); cp_commit();

    for (int c = 0; c < nchunk; c++) {
        cp_wait1();
        __syncthreads();
        const unsigned stg = sb + (c & 1) * TG_STAGE;
        const bf16* sA_hi = (const bf16*)(smem_raw + (c & 1) * TG_STAGE);
        const bf16* sA_lo = sA_hi + 5120;
        const bf16* sB_hi = sA_hi + 10240;
        const bf16* sB_lo = sA_hi + 15360;

#pragma unroll
        for (int ks = 0; ks < 2; ks++) {
            unsigned ah[2][4], al[2][4];
#pragma unroll
            for (int mt = 0; mt < 2; mt++) {
                const int r = warpM * 32 + mt * 16 + (lane & 15);
                const int cc = ks * 16 + ((lane & 16) >> 1);
                ldsm_x4(ah[mt][0], ah[mt][1], ah[mt][2], ah[mt][3], saddr(sA_hi + r * 40 + cc));
                ldsm_x4(al[mt][0], al[mt][1], al[mt][2], al[mt][3], saddr(sA_lo + r * 40 + cc));
            }
#pragma unroll
            for (int ntp = 0; ntp < 4; ntp++) {
                const int r = warpN * 64 + ntp * 16 + (lane & 7) + ((lane & 16) >> 1);
                const int cc = ks * 16 + (lane & 8);
                unsigned bh[4], bl[4];
                ldsm_x4(bh[0], bh[1], bh[2], bh[3], saddr(sB_hi + r * 40 + cc));
                ldsm_x4(bl[0], bl[1], bl[2], bl[3], saddr(sB_lo + r * 40 + cc));
#pragma unroll
                for (int half = 0; half < 2; half++) {
                    const int nt = 2 * ntp + half;
#pragma unroll
                    for (int mt = 0; mt < 2; mt++) {
                        mma16816(acc[mt][nt], ah[mt][0], ah[mt][1], ah[mt][2], ah[mt][3],
                                 bh[2 * half], bh[2 * half + 1]);
                        mma16816(acc[mt][nt], ah[mt][0], ah[mt][1], ah[mt][2], ah[mt][3],
                                 bl[2 * half], bl[2 * half + 1]);
                        mma16816(acc[mt][nt], al[mt][0], al[mt][1], al[mt][2], al[mt][3],
                                 bh[2 * half], bh[2 * half + 1]);
                    }
                }
            }
        }
        __syncthreads();
        if (c + 2 < nchunk) load_stage(c + 2);
        cp_commit();
    }

    // ---- epilogue ----
#pragma unroll
    for (int mt = 0; mt < 2; mt++) {
#pragma unroll
        for (int half = 0; half < 2; half++) {
            const int r = brow + warpM * 32 + mt * 16 + (lane >> 2) + half * 8;
#pragma unroll
            for (int nt = 0; nt < 8; nt++) {
                const int c = bcol + warpN * 64 + nt * 8 + 2 * (lane & 3);
                float2 bv = *(const float2*)(bias + c);
                float x = acc[mt][nt][half * 2 + 0] + bv.x;
                float y = acc[mt][nt][half * 2 + 1] + bv.y;
                if (EPI == 1) {
                    float2 rv = *(const float2*)(resid + (size_t)r * N + c);
                    x += rv.x; y += rv.y;
                }
                if (EPI == 2) {
                    x = 0.5f * x * (1.0f + erff(x * 0.7071067811865475f));
                    y = 0.5f * y * (1.0f + erff(y * 0.7071067811865475f));
                }
                if (EPI == 1 || EPI == 3) {
                    float2 o2; o2.x = x; o2.y = y;
                    *(float2*)(Cf + (size_t)r * N + c) = o2;
                } else {
                    unsigned h, l;
                    split_pk(x, y, h, l);
                    *(unsigned*)(Chi + (size_t)r * N + c) = h;
                    *(unsigned*)(Clo + (size_t)r * N + c) = l;
                }
            }
        }
    }
}

// ---------------- flash attention: cp.async 2-stage KV pipeline ----------------
// Stage layout (bf16, 64 rows x 72 cols padded): kh | kl | vh | vl, 9216 B each.
#define AT_STAGE 36864
#define AT_SMEM (2 * AT_STAGE)
__global__ __launch_bounds__(128) void attn_mma(
    const bf16* __restrict__ Qh, const bf16* __restrict__ Ql,
    const bf16* __restrict__ Kh, const bf16* __restrict__ Kl,
    const bf16* __restrict__ Vh, const bf16* __restrict__ Vl,
    bf16* __restrict__ Ohi, bf16* __restrict__ Olo)
{
    extern __shared__ __align__(16) char smem_raw[];
    const int tid = threadIdx.x;
    const int lane = tid & 31;
    const int warp = tid >> 5;
    const int b = blockIdx.z;
    const int h = blockIdx.y;
    const int q0 = blockIdx.x * 64;
    const int hoff = h * HEAD_DIM;

    const bf16* Qbh = Qh + (size_t)(b * SEQ + q0) * D_MODEL + hoff;
    const bf16* Qbl = Ql + (size_t)(b * SEQ + q0) * D_MODEL + hoff;
    const bf16* Kbh = Kh + (size_t)(b * SEQ) * D_MODEL + hoff;
    const bf16* Kbl = Kl + (size_t)(b * SEQ) * D_MODEL + hoff;
    const bf16* Vbh = Vh + (size_t)(b * SEQ) * D_MODEL + hoff;
    const bf16* Vbl = Vl + (size_t)(b * SEQ) * D_MODEL + hoff;

    // ---- stage Q into stage-0 buffer, extract fragments ----
    {
        bf16* qhi = (bf16*)smem_raw;
        bf16* qlo = qhi + 4608;           // 64*72
#pragma unroll
        for (int i = 0; i < 4; i++) {
            const int cid = i * 128 + tid;
            const int row = cid >> 3;
            const int ch = cid & 7;
            *(uint4*)(qhi + row * 72 + 8 * ch) = *(const uint4*)(Qbh + (size_t)row * D_MODEL + 8 * ch);
            *(uint4*)(qlo + row * 72 + 8 * ch) = *(const uint4*)(Qbl + (size_t)row * D_MODEL + 8 * ch);
        }
    }
    __syncthreads();

    unsigned qh[4][4], ql[4][4];
    {
        const bf16* qhi = (const bf16*)smem_raw;
        const bf16* qlo = qhi + 4608;
        const int r = warp * 16 + (lane & 15);
#pragma unroll
        for (int ks = 0; ks < 4; ks++) {
            const int c = ks * 16 + ((lane & 16) >> 1);
            ldsm_x4(qh[ks][0], qh[ks][1], qh[ks][2], qh[ks][3], saddr(qhi + r * 72 + c));
            ldsm_x4(ql[ks][0], ql[ks][1], ql[ks][2], ql[ks][3], saddr(qlo + r * 72 + c));
        }
    }
    __syncthreads();

    const unsigned sb = saddr(smem_raw);
    auto load_kv = [&](int t) {
        const unsigned stg = sb + (t & 1) * AT_STAGE;
        const int kt = t * 64;
#pragma unroll
        for (int i = 0; i < 4; i++) {
            const int cid = i * 128 + tid;
            const int row = cid >> 3;
            const int ch = cid & 7;
            const unsigned so = (unsigned)(row * 144 + ch * 16);
            const size_t go = (size_t)(kt + row) * D_MODEL + 8 * ch;
            cp16(stg + so,         Kbh + go);
            cp16(stg + 9216 + so,  Kbl + go);
            cp16(stg + 18432 + so, Vbh + go);
            cp16(stg + 27648 + so, Vbl + go);
        }
    };

    float o[8][4];
#pragma unroll
    for (int jd = 0; jd < 8; jd++)
#pragma unroll
        for (int i = 0; i < 4; i++) o[jd][i] = 0.0f;
    float run_m1 = -1e30f, run_m2 = -1e30f, run_l1 = 0.0f, run_l2 = 0.0f;

    load_kv(0); cp_commit();
    load_kv(1); cp_commit();

    const int ntiles = SEQ / 64;
    for (int t = 0; t < ntiles; t++) {
        cp_wait1();
        __syncthreads();
        const bf16* skh = (const bf16*)(smem_raw + (t & 1) * AT_STAGE);
        const bf16* skl = skh + 4608;
        const bf16* svh = skh + 9216;
        const bf16* svl = skh + 13824;

        // ---- S = Q K^T ----
        float s[8][4];
#pragma unroll
        for (int j = 0; j < 8; j++)
#pragma unroll
            for (int i = 0; i < 4; i++) s[j][i] = 0.0f;
#pragma unroll
        for (int ks = 0; ks < 4; ks++) {
#pragma unroll
            for (int ntp = 0; ntp < 4; ntp++) {
                const int r = ntp * 16 + (lane & 7) + ((lane & 16) >> 1);
                const int c = ks * 16 + (lane & 8);
                unsigned bh[4], bl[4];
                ldsm_x4(bh[0], bh[1], bh[2], bh[3], saddr(skh + r * 72 + c));
                ldsm_x4(bl[0], bl[1], bl[2], bl[3], saddr(skl + r * 72 + c));
#pragma unroll
                for (int half = 0; half < 2; half++) {
                    const int j = 2 * ntp + half;
                    mma16816(s[j], qh[ks][0], qh[ks][1], qh[ks][2], qh[ks][3],
                             bh[2 * half], bh[2 * half + 1]);
                    mma16816(s[j], qh[ks][0], qh[ks][1], qh[ks][2], qh[ks][3],
                             bl[2 * half], bl[2 * half + 1]);
                    mma16816(s[j], ql[ks][0], ql[ks][1], ql[ks][2], ql[ks][3],
                             bh[2 * half], bh[2 * half + 1]);
                }
            }
        }
#pragma unroll
        for (int j = 0; j < 8; j++)
#pragma unroll
            for (int i = 0; i < 4; i++) s[j][i] *= 0.125f;

        // ---- online softmax ----
        float tm1 = -1e30f, tm2 = -1e30f;
#pragma unroll
        for (int j = 0; j < 8; j++) {
            tm1 = fmaxf(tm1, fmaxf(s[j][0], s[j][1]));
            tm2 = fmaxf(tm2, fmaxf(s[j][2], s[j][3]));
        }
        tm1 = fmaxf(tm1, __shfl_xor_sync(0xffffffffu, tm1, 1));
        tm1 = fmaxf(tm1, __shfl_xor_sync(0xffffffffu, tm1, 2));
        tm2 = fmaxf(tm2, __shfl_xor_sync(0xffffffffu, tm2, 1));
        tm2 = fmaxf(tm2, __shfl_xor_sync(0xffffffffu, tm2, 2));
        const float nm1 = fmaxf(run_m1, tm1);
        const float nm2 = fmaxf(run_m2, tm2);
        const float sc1 = __expf(run_m1 - nm1);
        const float sc2 = __expf(run_m2 - nm2);
        run_m1 = nm1; run_m2 = nm2;

        float ts1 = 0.0f, ts2 = 0.0f;
#pragma unroll
        for (int j = 0; j < 8; j++) {
            s[j][0] = __expf(s[j][0] - nm1);
            s[j][1] = __expf(s[j][1] - nm1);
            s[j][2] = __expf(s[j][2] - nm2);
            s[j][3] = __expf(s[j][3] - nm2);
            ts1 += s[j][0] + s[j][1];
            ts2 += s[j][2] + s[j][3];
        }
        ts1 += __shfl_xor_sync(0xffffffffu, ts1, 1);
        ts1 += __shfl_xor_sync(0xffffffffu, ts1, 2);
        ts2 += __shfl_xor_sync(0xffffffffu, ts2, 1);
        ts2 += __shfl_xor_sync(0xffffffffu, ts2, 2);
        run_l1 = run_l1 * sc1 + ts1;
        run_l2 = run_l2 * sc2 + ts2;
#pragma unroll
        for (int jd = 0; jd < 8; jd++) {
            o[jd][0] *= sc1; o[jd][1] *= sc1;
            o[jd][2] *= sc2; o[jd][3] *= sc2;
        }

        // ---- O += P V ----
#pragma unroll
        for (int kp = 0; kp < 4; kp++) {
            unsigned ph_[4], pl_[4];
            split_pk(s[2 * kp][0],     s[2 * kp][1],     ph_[0], pl_[0]);
            split_pk(s[2 * kp][2],     s[2 * kp][3],     ph_[1], pl_[1]);
            split_pk(s[2 * kp + 1][0], s[2 * kp + 1][1], ph_[2], pl_[2]);
            split_pk(s[2 * kp + 1][2], s[2 * kp + 1][3], ph_[3], pl_[3]);
#pragma unroll
            for (int dntp = 0; dntp < 4; dntp++) {
                const int r = kp * 16 + (lane & 15);
                const int c = dntp * 16 + ((lane & 16) >> 1);
                unsigned vh[4], vl[4];
                ldsm_x4_t(vh[0], vh[1], vh[2], vh[3], saddr(svh + r * 72 + c));
                ldsm_x4_t(vl[0], vl[1], vl[2], vl[3], saddr(svl + r * 72 + c));
#pragma unroll
                for (int half = 0; half < 2; half++) {
                    const int jd = 2 * dntp + half;
                    mma16816(o[jd], ph_[0], ph_[1], ph_[2], ph_[3], vh[2 * half], vh[2 * half + 1]);
                    mma16816(o[jd], ph_[0], ph_[1], ph_[2], ph_[3], vl[2 * half], vl[2 * half + 1]);
                    mma16816(o[jd], pl_[0], pl_[1], pl_[2], pl_[3], vh[2 * half], vh[2 * half + 1]);
                }
            }
        }
        __syncthreads();
        if (t + 2 < ntiles) load_kv(t + 2);
        cp_commit();
    }

    // ---- write O as split bf16 ----
    const float i1 = 1.0f / run_l1;
    const float i2 = 1.0f / run_l2;
    const int r1 = b * SEQ + q0 + warp * 16 + (lane >> 2);
#pragma unroll
    for (int jd = 0; jd < 8; jd++) {
        const int c = hoff + jd * 8 + 2 * (lane & 3);
        unsigned h0, l0, h1, l1;
        split_pk(o[jd][0] * i1, o[jd][1] * i1, h0, l0);
        split_pk(o[jd][2] * i2, o[jd][3] * i2, h1, l1);
        *(unsigned*)(Ohi + (size_t)r1 * D_MODEL + c) = h0;
        *(unsigned*)(Olo + (size_t)r1 * D_MODEL + c) = l0;
        *(unsigned*)(Ohi + (size_t)(r1 + 8) * D_MODEL + c) = h1;
        *(unsigned*)(Olo + (size_t)(r1 + 8) * D_MODEL + c) = l1;
    }
}

// ---------------- LayerNorm: OUT=0 fp32 out, OUT=1 split-bf16 out ----------------
template <int OUT>
__global__ __launch_bounds__(256) void ln_kernel(
    const float* __restrict__ x, const float* __restrict__ w,
    const float* __restrict__ b, float* __restrict__ outf,
    bf16* __restrict__ outhi, bf16* __restrict__ outlo, int ldo)
{
    const int row = blockIdx.x;
    const int tid = threadIdx.x;

    float4 v = ((const float4*)(x + (size_t)row * D_MODEL))[tid];
    float s  = v.x + v.y + v.z + v.w;
    float s2 = v.x * v.x + v.y * v.y + v.z * v.z + v.w * v.w;
#pragma unroll
    for (int off = 16; off > 0; off >>= 1) {
        s  += __shfl_xor_sync(0xffffffffu, s, off);
        s2 += __shfl_xor_sync(0xffffffffu, s2, off);
    }
    __shared__ float rs[8], rs2[8];
    __shared__ float smu, sinv;
    const int wid = tid >> 5;
    if ((tid & 31) == 0) { rs[wid] = s; rs2[wid] = s2; }
    __syncthreads();
    if (tid == 0) {
        float ts = 0.0f, ts2 = 0.0f;
#pragma unroll
        for (int i = 0; i < 8; i++) { ts += rs[i]; ts2 += rs2[i]; }
        float mu  = ts * (1.0f / D_MODEL);
        float var = ts2 * (1.0f / D_MODEL) - mu * mu;
        smu = mu;
        sinv = rsqrtf(var + 1e-5f);
    }
    __syncthreads();
    const float mu = smu, inv = sinv;

    float4 wv = ((const float4*)w)[tid];
    float4 bv = ((const float4*)b)[tid];
    float4 ov;
    ov.x = (v.x - mu) * inv * wv.x + bv.x;
    ov.y = (v.y - mu) * inv * wv.y + bv.y;
    ov.z = (v.z - mu) * inv * wv.z + bv.z;
    ov.w = (v.w - mu) * inv * wv.w + bv.w;
    if (OUT == 0) {
        ((float4*)(outf + (size_t)row * ldo))[tid] = ov;
    } else {
        unsigned h0, l0, h1, l1;
        split_pk(ov.x, ov.y, h0, l0);
        split_pk(ov.z, ov.w, h1, l1);
        unsigned* ph = (unsigned*)(outhi + (size_t)row * ldo + 4 * tid);
        unsigned* pl = (unsigned*)(outlo + (size_t)row * ldo + 4 * tid);
        ph[0] = h0; ph[1] = h1;
        pl[0] = l0; pl[1] = l1;
    }
}

// ---------------- orchestration ----------------
extern "C" void kernel_launch(void* const* d_in, const int* in_sizes, int n_in,
                              void* d_out, int out_size)
{
    (void)in_sizes; (void)n_in; (void)out_size;

    const float* temporal = (const float*)d_in[0];
    const float* feature  = (const float*)d_in[1];
    const float* qt_w = (const float*)d_in[2];  const float* qt_b = (const float*)d_in[3];
    const float* kf_w = (const float*)d_in[4];  const float* kf_b = (const float*)d_in[5];
    const float* vf_w = (const float*)d_in[6];  const float* vf_b = (const float*)d_in[7];
    const float* qf_w = (const float*)d_in[8];  const float* qf_b = (const float*)d_in[9];
    const float* kt_w = (const float*)d_in[10]; const float* kt_b = (const float*)d_in[11];
    const float* vt_w = (const float*)d_in[12]; const float* vt_b = (const float*)d_in[13];
    const float* ot_w = (const float*)d_in[14]; const float* ot_b = (const float*)d_in[15];
    const float* of_w = (const float*)d_in[16]; const float* of_b = (const float*)d_in[17];
    const float* fus1_w = (const float*)d_in[18]; const float* fus1_b = (const float*)d_in[19];
    const float* fus2_w = (const float*)d_in[20]; const float* fus2_b = (const float*)d_in[21];
    const float* ln_fus_w = (const float*)d_in[22]; const float* ln_fus_b = (const float*)d_in[23];
    const float* ln_t_w = (const float*)d_in[24]; const float* ln_t_b = (const float*)d_in[25];
    const float* ln_f_w = (const float*)d_in[26]; const float* ln_f_b = (const float*)d_in[27];
    float* out = (float*)d_out;

    bf16 *xt_hi, *xt_lo, *xf_hi, *xf_lo, *qh, *ql, *kh, *kl, *vh, *vl, *ah, *al;
    bf16 *cat_hi, *cat_lo, *wp_hi, *wp_lo;
    float *t;
    cudaGetSymbolAddress((void**)&xt_hi, g_xt_hi); cudaGetSymbolAddress((void**)&xt_lo, g_xt_lo);
    cudaGetSymbolAddress((void**)&xf_hi, g_xf_hi); cudaGetSymbolAddress((void**)&xf_lo, g_xf_lo);
    cudaGetSymbolAddress((void**)&qh, g_qh); cudaGetSymbolAddress((void**)&ql, g_ql);
    cudaGetSymbolAddress((void**)&kh, g_kh); cudaGetSymbolAddress((void**)&kl, g_kl);
    cudaGetSymbolAddress((void**)&vh, g_vh); cudaGetSymbolAddress((void**)&vl, g_vl);
    cudaGetSymbolAddress((void**)&ah, g_ah); cudaGetSymbolAddress((void**)&al, g_al);
    cudaGetSymbolAddress((void**)&cat_hi, g_cat_hi); cudaGetSymbolAddress((void**)&cat_lo, g_cat_lo);
    cudaGetSymbolAddress((void**)&wp_hi, g_wp_hi); cudaGetSymbolAddress((void**)&wp_lo, g_wp_lo);
    cudaGetSymbolAddress((void**)&t, g_t);

    cudaFuncSetAttribute(tgemm<0>, cudaFuncAttributeMaxDynamicSharedMemorySize, TG_SMEM);
    cudaFuncSetAttribute(tgemm<1>, cudaFuncAttributeMaxDynamicSharedMemorySize, TG_SMEM);
    cudaFuncSetAttribute(tgemm<2>, cudaFuncAttributeMaxDynamicSharedMemorySize, TG_SMEM);
    cudaFuncSetAttribute(tgemm<3>, cudaFuncAttributeMaxDynamicSharedMemorySize, TG_SMEM);
    cudaFuncSetAttribute(attn_mma, cudaFuncAttributeMaxDynamicSharedMemorySize, AT_SMEM);

    const int nblk = (M_TOK * D_MODEL) / 1024;
    const dim3 tgrid(1024 / 32, 1024 / 32);
    const dim3 tgrid1(1024 / 32, 2048 / 32);
    const dim3 tblk(32, 8);
    const dim3 ggrid(D_MODEL / 128, M_TOK / 128);  // (8, 64)
    const dim3 agrid(SEQ / 64, N_HEADS, BATCH);    // (32, 16, 4)

    // ---- conversions ----
    split_kernel<<<nblk, 256>>>(temporal, xt_hi, xt_lo);
    split_kernel<<<nblk, 256>>>(feature,  xf_hi, xf_lo);
    wconv<<<tgrid, tblk>>>(qt_w, wp_hi + WOFF_QT, wp_lo + WOFF_QT, 1024, 1024);
    wconv<<<tgrid, tblk>>>(kf_w, wp_hi + WOFF_KF, wp_lo + WOFF_KF, 1024, 1024);
    wconv<<<tgrid, tblk>>>(vf_w, wp_hi + WOFF_VF, wp_lo + WOFF_VF, 1024, 1024);
    wconv<<<tgrid, tblk>>>(qf_w, wp_hi + WOFF_QF, wp_lo + WOFF_QF, 1024, 1024);
    wconv<<<tgrid, tblk>>>(kt_w, wp_hi + WOFF_KT, wp_lo + WOFF_KT, 1024, 1024);
    wconv<<<tgrid, tblk>>>(vt_w, wp_hi + WOFF_VT, wp_lo + WOFF_VT, 1024, 1024);
    wconv<<<tgrid, tblk>>>(ot_w, wp_hi + WOFF_OT, wp_lo + WOFF_OT, 1024, 1024);
    wconv<<<tgrid, tblk>>>(of_w, wp_hi + WOFF_OF, wp_lo + WOFF_OF, 1024, 1024);
    wconv<<<tgrid, tblk>>>(fus2_w, wp_hi + WOFF_F2, wp_lo + WOFF_F2, 1024, 1024);
    wconv<<<tgrid1, tblk>>>(fus1_w, wp_hi + WOFF_F1, wp_lo + WOFF_F1, 2048, 1024);

    // ---- temporal -> feature cross attention ----
    tgemm<0><<<ggrid, 256, TG_SMEM>>>(xt_hi, xt_lo, wp_hi + WOFF_QT, wp_lo + WOFF_QT, qt_b,
                                      nullptr, nullptr, qh, ql, M_TOK, D_MODEL, D_MODEL);
    tgemm<0><<<ggrid, 256, TG_SMEM>>>(xf_hi, xf_lo, wp_hi + WOFF_KF, wp_lo + WOFF_KF, kf_b,
                                      nullptr, nullptr, kh, kl, M_TOK, D_MODEL, D_MODEL);
    tgemm<0><<<ggrid, 256, TG_SMEM>>>(xf_hi, xf_lo, wp_hi + WOFF_VF, wp_lo + WOFF_VF, vf_b,
                                      nullptr, nullptr, vh, vl, M_TOK, D_MODEL, D_MODEL);
    attn_mma<<<agrid, 128, AT_SMEM>>>(qh, ql, kh, kl, vh, vl, ah, al);
    tgemm<1><<<ggrid, 256, TG_SMEM>>>(ah, al, wp_hi + WOFF_OT, wp_lo + WOFF_OT, ot_b,
                                      temporal, t, nullptr, nullptr, M_TOK, D_MODEL, D_MODEL);
    ln_kernel<1><<<M_TOK, 256>>>(t, ln_t_w, ln_t_b, nullptr, cat_hi, cat_lo, 2 * D_MODEL);

    // ---- feature -> temporal cross attention ----
    tgemm<0><<<ggrid, 256, TG_SMEM>>>(xf_hi, xf_lo, wp_hi + WOFF_QF, wp_lo + WOFF_QF, qf_b,
                                      nullptr, nullptr, qh, ql, M_TOK, D_MODEL, D_MODEL);
    tgemm<0><<<ggrid, 256, TG_SMEM>>>(xt_hi, xt_lo, wp_hi + WOFF_KT, wp_lo + WOFF_KT, kt_b,
                                      nullptr, nullptr, kh, kl, M_TOK, D_MODEL, D_MODEL);
    tgemm<0><<<ggrid, 256, TG_SMEM>>>(xt_hi, xt_lo, wp_hi + WOFF_VT, wp_lo + WOFF_VT, vt_b,
                                      nullptr, nullptr, vh, vl, M_TOK, D_MODEL, D_MODEL);
    attn_mma<<<agrid, 128, AT_SMEM>>>(qh, ql, kh, kl, vh, vl, ah, al);
    tgemm<1><<<ggrid, 256, TG_SMEM>>>(ah, al, wp_hi + WOFF_OF, wp_lo + WOFF_OF, of_b,
                                      feature, t, nullptr, nullptr, M_TOK, D_MODEL, D_MODEL);
    ln_kernel<1><<<M_TOK, 256>>>(t, ln_f_w, ln_f_b, nullptr, cat_hi + D_MODEL, cat_lo + D_MODEL,
                                 2 * D_MODEL);

    // ---- fusion MLP ----
    tgemm<2><<<ggrid, 256, TG_SMEM>>>(cat_hi, cat_lo, wp_hi + WOFF_F1, wp_lo + WOFF_F1,
                                      fus1_b, nullptr, nullptr, qh, ql,
                                      M_TOK, D_MODEL, 2 * D_MODEL);
    tgemm<3><<<ggrid, 256, TG_SMEM>>>(qh, ql, wp_hi + WOFF_F2, wp_lo + WOFF_F2, fus2_b,
                                      nullptr, t, nullptr, nullptr, M_TOK, D_MODEL, D_MODEL);
    ln_kernel<0><<<M_TOK, 256>>>(t, ln_fus_w, ln_fus_b, out, nullptr, nullptr, D_MODEL);
}

// round 11
// speedup vs baseline: 3.8686x; 1.0139x over previous
#include <cuda_runtime.h>
#include <cuda_bf16.h>
#include <math.h>
#include <stdint.h>

#define D_MODEL 1024
#define N_HEADS 16
#define HEAD_DIM 64
#define BATCH 4
#define SEQ 2048
#define M_TOK (BATCH * SEQ) /* 8192 */

typedef __nv_bfloat16 bf16;

#define NELEM ((size_t)M_TOK * D_MODEL)

// ---------------- scratch (allocation-free: __device__ globals) ----------------
__device__ bf16 g_xt_hi[NELEM], g_xt_lo[NELEM];
__device__ bf16 g_xf_hi[NELEM], g_xf_lo[NELEM];
__device__ bf16 g_q1h[NELEM], g_q1l[NELEM], g_k1h[NELEM], g_k1l[NELEM], g_v1h[NELEM], g_v1l[NELEM];
__device__ bf16 g_q2h[NELEM], g_q2l[NELEM], g_k2h[NELEM], g_k2l[NELEM], g_v2h[NELEM], g_v2l[NELEM];
__device__ bf16 g_a1h[NELEM], g_a1l[NELEM], g_a2h[NELEM], g_a2l[NELEM];
__device__ bf16 g_cat_hi[2 * NELEM], g_cat_lo[2 * NELEM];
__device__ float g_t1[NELEM], g_t2[NELEM];
__device__ bf16 g_wp_hi[11u * 1024u * 1024u];
__device__ bf16 g_wp_lo[11u * 1024u * 1024u];

// pool layout (element offsets); QT,KT,VT and QF,KF,VF and OT,OF adjacent
#define WOFF_QT 0u
#define WOFF_KT (1u * 1048576u)
#define WOFF_VT (2u * 1048576u)
#define WOFF_QF (3u * 1048576u)
#define WOFF_KF (4u * 1048576u)
#define WOFF_VF (5u * 1048576u)
#define WOFF_OT (6u * 1048576u)
#define WOFF_OF (7u * 1048576u)
#define WOFF_F2 (8u * 1048576u)
#define WOFF_F1 (9u * 1048576u)

// ---------------- helpers ----------------
__device__ __forceinline__ void split_pk(float a, float b, unsigned &hi, unsigned &lo) {
    bf16 ah = __float2bfloat16_rn(a);
    bf16 bh = __float2bfloat16_rn(b);
    hi = ((unsigned)__bfloat16_as_ushort(bh) << 16) | (unsigned)__bfloat16_as_ushort(ah);
    float ar = a - __bfloat162float(ah);
    float br = b - __bfloat162float(bh);
    lo = ((unsigned)__bfloat16_as_ushort(__float2bfloat16_rn(br)) << 16) |
         (unsigned)__bfloat16_as_ushort(__float2bfloat16_rn(ar));
}

__device__ __forceinline__ void mma16816(float* d, unsigned a0, unsigned a1,
                                         unsigned a2, unsigned a3,
                                         unsigned b0, unsigned b1) {
    asm volatile(
        "mma.sync.aligned.m16n8k16.row.col.f32.bf16.bf16.f32 "
        "{%0,%1,%2,%3},{%4,%5,%6,%7},{%8,%9},{%0,%1,%2,%3};"
        : "+f"(d[0]), "+f"(d[1]), "+f"(d[2]), "+f"(d[3])
        : "r"(a0), "r"(a1), "r"(a2), "r"(a3), "r"(b0), "r"(b1));
}

__device__ __forceinline__ unsigned saddr(const void* p) {
    return (unsigned)__cvta_generic_to_shared(p);
}
__device__ __forceinline__ void ldsm_x4(unsigned &r0, unsigned &r1, unsigned &r2,
                                        unsigned &r3, unsigned a) {
    asm volatile("ldmatrix.sync.aligned.m8n8.x4.shared.b16 {%0,%1,%2,%3},[%4];"
                 : "=r"(r0), "=r"(r1), "=r"(r2), "=r"(r3) : "r"(a));
}
__device__ __forceinline__ void ldsm_x4_t(unsigned &r0, unsigned &r1, unsigned &r2,
                                          unsigned &r3, unsigned a) {
    asm volatile("ldmatrix.sync.aligned.m8n8.x4.trans.shared.b16 {%0,%1,%2,%3},[%4];"
                 : "=r"(r0), "=r"(r1), "=r"(r2), "=r"(r3) : "r"(a));
}
__device__ __forceinline__ void cp16(unsigned dst, const void* src) {
    asm volatile("cp.async.cg.shared.global [%0], [%1], 16;" :: "r"(dst), "l"(src));
}
__device__ __forceinline__ void cp_commit() {
    asm volatile("cp.async.commit_group;");
}
__device__ __forceinline__ void cp_wait1() {
    asm volatile("cp.async.wait_group 1;" ::: "memory");
}

// ---------------- converters ----------------
__global__ __launch_bounds__(256) void split_kernel(
    const float* __restrict__ in, bf16* __restrict__ hi, bf16* __restrict__ lo)
{
    const size_t i = (size_t)blockIdx.x * 256 + threadIdx.x;
    float4 v = ((const float4*)in)[i];
    unsigned h0, l0, h1, l1;
    split_pk(v.x, v.y, h0, l0);
    split_pk(v.z, v.w, h1, l1);
    uint2 hh; hh.x = h0; hh.y = h1;
    uint2 ll; ll.x = l0; ll.y = l1;
    ((uint2*)hi)[i] = hh;
    ((uint2*)lo)[i] = ll;
}

// W[K][N] fp32 -> T[N][K] split bf16
__global__ __launch_bounds__(256) void wconv(
    const float* __restrict__ W, bf16* __restrict__ Thi, bf16* __restrict__ Tlo,
    int K, int N)
{
    __shared__ float tile[32][33];
    const int tx = threadIdx.x, ty = threadIdx.y;
    const int n0 = blockIdx.x * 32;
    const int k0 = blockIdx.y * 32;
#pragma unroll
    for (int i = 0; i < 4; i++)
        tile[ty + 8 * i][tx] = W[(size_t)(k0 + ty + 8 * i) * N + n0 + tx];
    __syncthreads();
#pragma unroll
    for (int i = 0; i < 4; i++) {
        float v = tile[tx][ty + 8 * i];
        bf16 h = __float2bfloat16_rn(v);
        const size_t o = (size_t)(n0 + ty + 8 * i) * K + k0 + tx;
        Thi[o] = h;
        Tlo[o] = __float2bfloat16_rn(v - __bfloat162float(h));
    }
}

// ---------------- shared GEMM mainloop (cp.async 2-stage, split-bf16 mma) ----------
// A rows [brow, brow+128) of [.][K]; B rows [browB, browB+128) of [.][K].
#define TG_STAGE 40960
#define TG_SMEM (2 * TG_STAGE)
__device__ __forceinline__ void gemm_mainloop(
    const bf16* __restrict__ Ahi, const bf16* __restrict__ Alo,
    const bf16* __restrict__ Bhi, const bf16* __restrict__ Blo,
    int brow, int browB, int K, char* smem_raw, float acc[2][8][4])
{
    const int tid = threadIdx.x;
    const int lane = tid & 31;
    const int wid = tid >> 5;
    const int warpM = wid & 3;
    const int warpN = wid >> 2;
    const unsigned sb = saddr(smem_raw);
    const int nchunk = K >> 5;

#pragma unroll
    for (int mt = 0; mt < 2; mt++)
#pragma unroll
        for (int nt = 0; nt < 8; nt++)
#pragma unroll
            for (int i = 0; i < 4; i++) acc[mt][nt][i] = 0.0f;

    auto load_stage = [&](int c) {
        const unsigned stg = sb + (c & 1) * TG_STAGE;
        const int k0 = c * 32;
#pragma unroll
        for (int q = 0; q < 2; q++) {
            const int cid = tid * 2 + q;
            const int r = cid >> 2;
            const int cb = cid & 3;
            const unsigned so = (unsigned)(r * 80 + cb * 16);
            const size_t goA = (size_t)(brow + r) * K + k0 + cb * 8;
            const size_t goB = (size_t)(browB + r) * K + k0 + cb * 8;
            cp16(stg + so,          Ahi + goA);
            cp16(stg + 10240 + so,  Alo + goA);
            cp16(stg + 20480 + so,  Bhi + goB);
            cp16(stg + 30720 + so,  Blo + goB);
        }
    };

    load_stage(0); cp_commit();
    load_stage(1); cp_commit();

    for (int c = 0; c < nchunk; c++) {
        cp_wait1();
        __syncthreads();
        const bf16* sA_hi = (const bf16*)(smem_raw + (c & 1) * TG_STAGE);
        const bf16* sA_lo = sA_hi + 5120;
        const bf16* sB_hi = sA_hi + 10240;
        const bf16* sB_lo = sA_hi + 15360;

#pragma unroll
        for (int ks = 0; ks < 2; ks++) {
            unsigned ah[2][4], al[2][4];
#pragma unroll
            for (int mt = 0; mt < 2; mt++) {
                const int r = warpM * 32 + mt * 16 + (lane & 15);
                const int cc = ks * 16 + ((lane & 16) >> 1);
                ldsm_x4(ah[mt][0], ah[mt][1], ah[mt][2], ah[mt][3], saddr(sA_hi + r * 40 + cc));
                ldsm_x4(al[mt][0], al[mt][1], al[mt][2], al[mt][3], saddr(sA_lo + r * 40 + cc));
            }
#pragma unroll
            for (int ntp = 0; ntp < 4; ntp++) {
                const int r = warpN * 64 + ntp * 16 + (lane & 7) + ((lane & 16) >> 1);
                const int cc = ks * 16 + (lane & 8);
                unsigned bh[4], bl[4];
                ldsm_x4(bh[0], bh[1], bh[2], bh[3], saddr(sB_hi + r * 40 + cc));
                ldsm_x4(bl[0], bl[1], bl[2], bl[3], saddr(sB_lo + r * 40 + cc));
#pragma unroll
                for (int half = 0; half < 2; half++) {
                    const int nt = 2 * ntp + half;
#pragma unroll
                    for (int mt = 0; mt < 2; mt++) {
                        mma16816(acc[mt][nt], ah[mt][0], ah[mt][1], ah[mt][2], ah[mt][3],
                                 bh[2 * half], bh[2 * half + 1]);
                        mma16816(acc[mt][nt], ah[mt][0], ah[mt][1], ah[mt][2], ah[mt][3],
                                 bl[2 * half], bl[2 * half + 1]);
                        mma16816(acc[mt][nt], al[mt][0], al[mt][1], al[mt][2], al[mt][3],
                                 bh[2 * half], bh[2 * half + 1]);
                    }
                }
            }
        }
        __syncthreads();
        if (c + 2 < nchunk) load_stage(c + 2);
        cp_commit();
    }
}

// ---------------- fused QKV projection GEMM: N=3072, split-bf16 outputs ----------
__global__ __launch_bounds__(256, 2) void tgemm_qkv(
    const bf16* __restrict__ Ahi, const bf16* __restrict__ Alo,
    const bf16* __restrict__ Bhi, const bf16* __restrict__ Blo,
    const float* __restrict__ b0, const float* __restrict__ b1, const float* __restrict__ b2,
    bf16* __restrict__ o0h, bf16* __restrict__ o0l,
    bf16* __restrict__ o1h, bf16* __restrict__ o1l,
    bf16* __restrict__ o2h, bf16* __restrict__ o2l)
{
    extern __shared__ __align__(16) char smem_raw[];
    const int brow = blockIdx.y * 128;
    const int bcol = blockIdx.x * 128;
    float acc[2][8][4];
    gemm_mainloop(Ahi, Alo, Bhi, Blo, brow, bcol, D_MODEL, smem_raw, acc);

    const int sel = bcol >> 10;
    const int ccol = bcol & 1023;
    const float* bias = (sel == 0) ? b0 : (sel == 1) ? b1 : b2;
    bf16* Chi = (sel == 0) ? o0h : (sel == 1) ? o1h : o2h;
    bf16* Clo = (sel == 0) ? o0l : (sel == 1) ? o1l : o2l;

    const int lane = threadIdx.x & 31;
    const int wid = threadIdx.x >> 5;
    const int warpM = wid & 3;
    const int warpN = wid >> 2;
#pragma unroll
    for (int mt = 0; mt < 2; mt++)
#pragma unroll
        for (int half = 0; half < 2; half++) {
            const int r = brow + warpM * 32 + mt * 16 + (lane >> 2) + half * 8;
#pragma unroll
            for (int nt = 0; nt < 8; nt++) {
                const int c = ccol + warpN * 64 + nt * 8 + 2 * (lane & 3);
                float2 bv = *(const float2*)(bias + c);
                float x = acc[mt][nt][half * 2 + 0] + bv.x;
                float y = acc[mt][nt][half * 2 + 1] + bv.y;
                unsigned h, l;
                split_pk(x, y, h, l);
                *(unsigned*)(Chi + (size_t)r * D_MODEL + c) = h;
                *(unsigned*)(Clo + (size_t)r * D_MODEL + c) = l;
            }
        }
}

// ---------------- fused O-projection GEMM (z selects branch), resid, fp32 out ----
__global__ __launch_bounds__(256, 2) void tgemm_o(
    const bf16* __restrict__ A1h, const bf16* __restrict__ A1l,
    const bf16* __restrict__ A2h, const bf16* __restrict__ A2l,
    const bf16* __restrict__ Bhi, const bf16* __restrict__ Blo,  // base = OT; OF adjacent
    const float* __restrict__ b1, const float* __restrict__ b2,
    const float* __restrict__ r1, const float* __restrict__ r2,
    float* __restrict__ t1, float* __restrict__ t2)
{
    extern __shared__ __align__(16) char smem_raw[];
    const int z = blockIdx.z;
    const int brow = blockIdx.y * 128;
    const int bcol = blockIdx.x * 128;
    const bf16* Ahi = z ? A2h : A1h;
    const bf16* Alo = z ? A2l : A1l;
    const float* bias = z ? b2 : b1;
    const float* resid = z ? r2 : r1;
    float* Cf = z ? t2 : t1;

    float acc[2][8][4];
    gemm_mainloop(Ahi, Alo, Bhi, Blo, brow, z * 1024 + bcol, D_MODEL, smem_raw, acc);

    const int lane = threadIdx.x & 31;
    const int wid = threadIdx.x >> 5;
    const int warpM = wid & 3;
    const int warpN = wid >> 2;
#pragma unroll
    for (int mt = 0; mt < 2; mt++)
#pragma unroll
        for (int half = 0; half < 2; half++) {
            const int r = brow + warpM * 32 + mt * 16 + (lane >> 2) + half * 8;
#pragma unroll
            for (int nt = 0; nt < 8; nt++) {
                const int c = bcol + warpN * 64 + nt * 8 + 2 * (lane & 3);
                float2 bv = *(const float2*)(bias + c);
                float2 rv = *(const float2*)(resid + (size_t)r * D_MODEL + c);
                float2 o2;
                o2.x = acc[mt][nt][half * 2 + 0] + bv.x + rv.x;
                o2.y = acc[mt][nt][half * 2 + 1] + bv.y + rv.y;
                *(float2*)(Cf + (size_t)r * D_MODEL + c) = o2;
            }
        }
}

// ---------------- standard GEMM: EPI 2 = bias+GELU->split; EPI 3 = bias->fp32 ----
template <int EPI>
__global__ __launch_bounds__(256, 2) void tgemm(
    const bf16* __restrict__ Ahi, const bf16* __restrict__ Alo,
    const bf16* __restrict__ Bhi, const bf16* __restrict__ Blo,
    const float* __restrict__ bias,
    float* __restrict__ Cf, bf16* __restrict__ Chi, bf16* __restrict__ Clo, int K)
{
    extern __shared__ __align__(16) char smem_raw[];
    const int brow = blockIdx.y * 128;
    const int bcol = blockIdx.x * 128;
    float acc[2][8][4];
    gemm_mainloop(Ahi, Alo, Bhi, Blo, brow, bcol, K, smem_raw, acc);

    const int lane = threadIdx.x & 31;
    const int wid = threadIdx.x >> 5;
    const int warpM = wid & 3;
    const int warpN = wid >> 2;
#pragma unroll
    for (int mt = 0; mt < 2; mt++)
#pragma unroll
        for (int half = 0; half < 2; half++) {
            const int r = brow + warpM * 32 + mt * 16 + (lane >> 2) + half * 8;
#pragma unroll
            for (int nt = 0; nt < 8; nt++) {
                const int c = bcol + warpN * 64 + nt * 8 + 2 * (lane & 3);
                float2 bv = *(const float2*)(bias + c);
                float x = acc[mt][nt][half * 2 + 0] + bv.x;
                float y = acc[mt][nt][half * 2 + 1] + bv.y;
                if (EPI == 2) {
                    x = 0.5f * x * (1.0f + erff(x * 0.7071067811865475f));
                    y = 0.5f * y * (1.0f + erff(y * 0.7071067811865475f));
                    unsigned h, l;
                    split_pk(x, y, h, l);
                    *(unsigned*)(Chi + (size_t)r * D_MODEL + c) = h;
                    *(unsigned*)(Clo + (size_t)r * D_MODEL + c) = l;
                } else {
                    float2 o2; o2.x = x; o2.y = y;
                    *(float2*)(Cf + (size_t)r * D_MODEL + c) = o2;
                }
            }
        }
}

// ---------------- merged flash attention (z selects branch+batch) ----------------
#define AT_STAGE 36864
#define AT_SMEM (2 * AT_STAGE)
__global__ __launch_bounds__(128) void attn_mma(
    const bf16* __restrict__ Q1h, const bf16* __restrict__ Q1l,
    const bf16* __restrict__ K1h, const bf16* __restrict__ K1l,
    const bf16* __restrict__ V1h, const bf16* __restrict__ V1l,
    bf16* __restrict__ O1h, bf16* __restrict__ O1l,
    const bf16* __restrict__ Q2h, const bf16* __restrict__ Q2l,
    const bf16* __restrict__ K2h, const bf16* __restrict__ K2l,
    const bf16* __restrict__ V2h, const bf16* __restrict__ V2l,
    bf16* __restrict__ O2h, bf16* __restrict__ O2l)
{
    extern __shared__ __align__(16) char smem_raw[];
    const int tid = threadIdx.x;
    const int lane = tid & 31;
    const int warp = tid >> 5;
    const int z = blockIdx.z;
    const int half2sel = z >> 2;
    const int b = z & 3;
    const int h = blockIdx.y;
    const int q0 = blockIdx.x * 64;
    const int hoff = h * HEAD_DIM;

    const bf16* Qh = half2sel ? Q2h : Q1h;
    const bf16* Ql_ = half2sel ? Q2l : Q1l;
    const bf16* Kh = half2sel ? K2h : K1h;
    const bf16* Kl = half2sel ? K2l : K1l;
    const bf16* Vh = half2sel ? V2h : V1h;
    const bf16* Vl = half2sel ? V2l : V1l;
    bf16* Ohi = half2sel ? O2h : O1h;
    bf16* Olo = half2sel ? O2l : O1l;

    const bf16* Qbh = Qh + (size_t)(b * SEQ + q0) * D_MODEL + hoff;
    const bf16* Qbl = Ql_ + (size_t)(b * SEQ + q0) * D_MODEL + hoff;
    const bf16* Kbh = Kh + (size_t)(b * SEQ) * D_MODEL + hoff;
    const bf16* Kbl = Kl + (size_t)(b * SEQ) * D_MODEL + hoff;
    const bf16* Vbh = Vh + (size_t)(b * SEQ) * D_MODEL + hoff;
    const bf16* Vbl = Vl + (size_t)(b * SEQ) * D_MODEL + hoff;

    // ---- stage Q into stage-0 buffer, extract fragments ----
    {
        bf16* qhi = (bf16*)smem_raw;
        bf16* qlo = qhi + 4608;
#pragma unroll
        for (int i = 0; i < 4; i++) {
            const int cid = i * 128 + tid;
            const int row = cid >> 3;
            const int ch = cid & 7;
            *(uint4*)(qhi + row * 72 + 8 * ch) = *(const uint4*)(Qbh + (size_t)row * D_MODEL + 8 * ch);
            *(uint4*)(qlo + row * 72 + 8 * ch) = *(const uint4*)(Qbl + (size_t)row * D_MODEL + 8 * ch);
        }
    }
    __syncthreads();

    unsigned qh[4][4], ql[4][4];
    {
        const bf16* qhi = (const bf16*)smem_raw;
        const bf16* qlo = qhi + 4608;
        const int r = warp * 16 + (lane & 15);
#pragma unroll
        for (int ks = 0; ks < 4; ks++) {
            const int c = ks * 16 + ((lane & 16) >> 1);
            ldsm_x4(qh[ks][0], qh[ks][1], qh[ks][2], qh[ks][3], saddr(qhi + r * 72 + c));
            ldsm_x4(ql[ks][0], ql[ks][1], ql[ks][2], ql[ks][3], saddr(qlo + r * 72 + c));
        }
    }
    __syncthreads();

    const unsigned sb = saddr(smem_raw);
    auto load_kv = [&](int t) {
        const unsigned stg = sb + (t & 1) * AT_STAGE;
        const int kt = t * 64;
#pragma unroll
        for (int i = 0; i < 4; i++) {
            const int cid = i * 128 + tid;
            const int row = cid >> 3;
            const int ch = cid & 7;
            const unsigned so = (unsigned)(row * 144 + ch * 16);
            const size_t go = (size_t)(kt + row) * D_MODEL + 8 * ch;
            cp16(stg + so,         Kbh + go);
            cp16(stg + 9216 + so,  Kbl + go);
            cp16(stg + 18432 + so, Vbh + go);
            cp16(stg + 27648 + so, Vbl + go);
        }
    };

    float o[8][4];
#pragma unroll
    for (int jd = 0; jd < 8; jd++)
#pragma unroll
        for (int i = 0; i < 4; i++) o[jd][i] = 0.0f;
    float run_m1 = -1e30f, run_m2 = -1e30f, run_l1 = 0.0f, run_l2 = 0.0f;

    load_kv(0); cp_commit();
    load_kv(1); cp_commit();

    const int ntiles = SEQ / 64;
    for (int t = 0; t < ntiles; t++) {
        cp_wait1();
        __syncthreads();
        const bf16* skh = (const bf16*)(smem_raw + (t & 1) * AT_STAGE);
        const bf16* skl = skh + 4608;
        const bf16* svh = skh + 9216;
        const bf16* svl = skh + 13824;

        float s[8][4];
#pragma unroll
        for (int j = 0; j < 8; j++)
#pragma unroll
            for (int i = 0; i < 4; i++) s[j][i] = 0.0f;
#pragma unroll
        for (int ks = 0; ks < 4; ks++) {
#pragma unroll
            for (int ntp = 0; ntp < 4; ntp++) {
                const int r = ntp * 16 + (lane & 7) + ((lane & 16) >> 1);
                const int c = ks * 16 + (lane & 8);
                unsigned bh[4], bl[4];
                ldsm_x4(bh[0], bh[1], bh[2], bh[3], saddr(skh + r * 72 + c));
                ldsm_x4(bl[0], bl[1], bl[2], bl[3], saddr(skl + r * 72 + c));
#pragma unroll
                for (int hf = 0; hf < 2; hf++) {
                    const int j = 2 * ntp + hf;
                    mma16816(s[j], qh[ks][0], qh[ks][1], qh[ks][2], qh[ks][3],
                             bh[2 * hf], bh[2 * hf + 1]);
                    mma16816(s[j], qh[ks][0], qh[ks][1], qh[ks][2], qh[ks][3],
                             bl[2 * hf], bl[2 * hf + 1]);
                    mma16816(s[j], ql[ks][0], ql[ks][1], ql[ks][2], ql[ks][3],
                             bh[2 * hf], bh[2 * hf + 1]);
                }
            }
        }
#pragma unroll
        for (int j = 0; j < 8; j++)
#pragma unroll
            for (int i = 0; i < 4; i++) s[j][i] *= 0.125f;

        float tm1 = -1e30f, tm2 = -1e30f;
#pragma unroll
        for (int j = 0; j < 8; j++) {
            tm1 = fmaxf(tm1, fmaxf(s[j][0], s[j][1]));
            tm2 = fmaxf(tm2, fmaxf(s[j][2], s[j][3]));
        }
        tm1 = fmaxf(tm1, __shfl_xor_sync(0xffffffffu, tm1, 1));
        tm1 = fmaxf(tm1, __shfl_xor_sync(0xffffffffu, tm1, 2));
        tm2 = fmaxf(tm2, __shfl_xor_sync(0xffffffffu, tm2, 1));
        tm2 = fmaxf(tm2, __shfl_xor_sync(0xffffffffu, tm2, 2));
        const float nm1 = fmaxf(run_m1, tm1);
        const float nm2 = fmaxf(run_m2, tm2);
        const float sc1 = __expf(run_m1 - nm1);
        const float sc2 = __expf(run_m2 - nm2);
        run_m1 = nm1; run_m2 = nm2;

        float ts1 = 0.0f, ts2 = 0.0f;
#pragma unroll
        for (int j = 0; j < 8; j++) {
            s[j][0] = __expf(s[j][0] - nm1);
            s[j][1] = __expf(s[j][1] - nm1);
            s[j][2] = __expf(s[j][2] - nm2);
            s[j][3] = __expf(s[j][3] - nm2);
            ts1 += s[j][0] + s[j][1];
            ts2 += s[j][2] + s[j][3];
        }
        ts1 += __shfl_xor_sync(0xffffffffu, ts1, 1);
        ts1 += __shfl_xor_sync(0xffffffffu, ts1, 2);
        ts2 += __shfl_xor_sync(0xffffffffu, ts2, 1);
        ts2 += __shfl_xor_sync(0xffffffffu, ts2, 2);
        run_l1 = run_l1 * sc1 + ts1;
        run_l2 = run_l2 * sc2 + ts2;
#pragma unroll
        for (int jd = 0; jd < 8; jd++) {
            o[jd][0] *= sc1; o[jd][1] *= sc1;
            o[jd][2] *= sc2; o[jd][3] *= sc2;
        }

#pragma unroll
        for (int kp = 0; kp < 4; kp++) {
            unsigned ph_[4], pl_[4];
            split_pk(s[2 * kp][0],     s[2 * kp][1],     ph_[0], pl_[0]);
            split_pk(s[2 * kp][2],     s[2 * kp][3],     ph_[1], pl_[1]);
            split_pk(s[2 * kp + 1][0], s[2 * kp + 1][1], ph_[2], pl_[2]);
            split_pk(s[2 * kp + 1][2], s[2 * kp + 1][3], ph_[3], pl_[3]);
#pragma unroll
            for (int dntp = 0; dntp < 4; dntp++) {
                const int r = kp * 16 + (lane & 15);
                const int c = dntp * 16 + ((lane & 16) >> 1);
                unsigned vh[4], vl[4];
                ldsm_x4_t(vh[0], vh[1], vh[2], vh[3], saddr(svh + r * 72 + c));
                ldsm_x4_t(vl[0], vl[1], vl[2], vl[3], saddr(svl + r * 72 + c));
#pragma unroll
                for (int hf = 0; hf < 2; hf++) {
                    const int jd = 2 * dntp + hf;
                    mma16816(o[jd], ph_[0], ph_[1], ph_[2], ph_[3], vh[2 * hf], vh[2 * hf + 1]);
                    mma16816(o[jd], ph_[0], ph_[1], ph_[2], ph_[3], vl[2 * hf], vl[2 * hf + 1]);
                    mma16816(o[jd], pl_[0], pl_[1], pl_[2], pl_[3], vh[2 * hf], vh[2 * hf + 1]);
                }
            }
        }
        __syncthreads();
        if (t + 2 < ntiles) load_kv(t + 2);
        cp_commit();
    }

    const float i1 = 1.0f / run_l1;
    const float i2 = 1.0f / run_l2;
    const int r1 = b * SEQ + q0 + warp * 16 + (lane >> 2);
#pragma unroll
    for (int jd = 0; jd < 8; jd++) {
        const int c = hoff + jd * 8 + 2 * (lane & 3);
        unsigned h0, l0, h1, l1;
        split_pk(o[jd][0] * i1, o[jd][1] * i1, h0, l0);
        split_pk(o[jd][2] * i2, o[jd][3] * i2, h1, l1);
        *(unsigned*)(Ohi + (size_t)r1 * D_MODEL + c) = h0;
        *(unsigned*)(Olo + (size_t)r1 * D_MODEL + c) = l0;
        *(unsigned*)(Ohi + (size_t)(r1 + 8) * D_MODEL + c) = h1;
        *(unsigned*)(Olo + (size_t)(r1 + 8) * D_MODEL + c) = l1;
    }
}

// ---------------- LayerNorm core ----------------
__device__ __forceinline__ float4 ln_core(const float* x, const float* w,
                                          const float* b, int row, int tid) {
    float4 v = ((const float4*)(x + (size_t)row * D_MODEL))[tid];
    float s  = v.x + v.y + v.z + v.w;
    float s2 = v.x * v.x + v.y * v.y + v.z * v.z + v.w * v.w;
#pragma unroll
    for (int off = 16; off > 0; off >>= 1) {
        s  += __shfl_xor_sync(0xffffffffu, s, off);
        s2 += __shfl_xor_sync(0xffffffffu, s2, off);
    }
    __shared__ float rs[8], rs2[8];
    __shared__ float smu, sinv;
    const int wd = tid >> 5;
    if ((tid & 31) == 0) { rs[wd] = s; rs2[wd] = s2; }
    __syncthreads();
    if (tid == 0) {
        float ts = 0.0f, ts2 = 0.0f;
#pragma unroll
        for (int i = 0; i < 8; i++) { ts += rs[i]; ts2 += rs2[i]; }
        float mu  = ts * (1.0f / D_MODEL);
        float var = ts2 * (1.0f / D_MODEL) - mu * mu;
        smu = mu;
        sinv = rsqrtf(var + 1e-5f);
    }
    __syncthreads();
    const float mu = smu, inv = sinv;
    float4 wv = ((const float4*)w)[tid];
    float4 bv = ((const float4*)b)[tid];
    float4 ov;
    ov.x = (v.x - mu) * inv * wv.x + bv.x;
    ov.y = (v.y - mu) * inv * wv.y + bv.y;
    ov.z = (v.z - mu) * inv * wv.z + bv.z;
    ov.w = (v.w - mu) * inv * wv.w + bv.w;
    return ov;
}

// merged post-attn LN: y selects branch; split-bf16 out into cat halves
__global__ __launch_bounds__(256) void ln2_kernel(
    const float* __restrict__ t1, const float* __restrict__ t2,
    const float* __restrict__ w1, const float* __restrict__ b1,
    const float* __restrict__ w2, const float* __restrict__ b2,
    bf16* __restrict__ cat_hi, bf16* __restrict__ cat_lo)
{
    const int row = blockIdx.x;
    const int sel = blockIdx.y;
    const int tid = threadIdx.x;
    float4 ov = ln_core(sel ? t2 : t1, sel ? w2 : w1, sel ? b2 : b1, row, tid);
    unsigned h0, l0, h1, l1;
    split_pk(ov.x, ov.y, h0, l0);
    split_pk(ov.z, ov.w, h1, l1);
    const size_t o = (size_t)row * 2048 + sel * 1024 + 4 * tid;
    unsigned* ph = (unsigned*)(cat_hi + o);
    unsigned* pl = (unsigned*)(cat_lo + o);
    ph[0] = h0; ph[1] = h1;
    pl[0] = l0; pl[1] = l1;
}

__global__ __launch_bounds__(256) void ln_final(
    const float* __restrict__ x, const float* __restrict__ w,
    const float* __restrict__ b, float* __restrict__ out)
{
    const int row = blockIdx.x;
    const int tid = threadIdx.x;
    float4 ov = ln_core(x, w, b, row, tid);
    ((float4*)(out + (size_t)row * D_MODEL))[tid] = ov;
}

// ---------------- orchestration ----------------
extern "C" void kernel_launch(void* const* d_in, const int* in_sizes, int n_in,
                              void* d_out, int out_size)
{
    (void)in_sizes; (void)n_in; (void)out_size;

    const float* temporal = (const float*)d_in[0];
    const float* feature  = (const float*)d_in[1];
    const float* qt_w = (const float*)d_in[2];  const float* qt_b = (const float*)d_in[3];
    const float* kf_w = (const float*)d_in[4];  const float* kf_b = (const float*)d_in[5];
    const float* vf_w = (const float*)d_in[6];  const float* vf_b = (const float*)d_in[7];
    const float* qf_w = (const float*)d_in[8];  const float* qf_b = (const float*)d_in[9];
    const float* kt_w = (const float*)d_in[10]; const float* kt_b = (const float*)d_in[11];
    const float* vt_w = (const float*)d_in[12]; const float* vt_b = (const float*)d_in[13];
    const float* ot_w = (const float*)d_in[14]; const float* ot_b = (const float*)d_in[15];
    const float* of_w = (const float*)d_in[16]; const float* of_b = (const float*)d_in[17];
    const float* fus1_w = (const float*)d_in[18]; const float* fus1_b = (const float*)d_in[19];
    const float* fus2_w = (const float*)d_in[20]; const float* fus2_b = (const float*)d_in[21];
    const float* ln_fus_w = (const float*)d_in[22]; const float* ln_fus_b = (const float*)d_in[23];
    const float* ln_t_w = (const float*)d_in[24]; const float* ln_t_b = (const float*)d_in[25];
    const float* ln_f_w = (const float*)d_in[26]; const float* ln_f_b = (const float*)d_in[27];
    float* out = (float*)d_out;

    bf16 *xt_hi, *xt_lo, *xf_hi, *xf_lo;
    bf16 *q1h, *q1l, *k1h, *k1l, *v1h, *v1l, *q2h, *q2l, *k2h, *k2l, *v2h, *v2l;
    bf16 *a1h, *a1l, *a2h, *a2l, *cat_hi, *cat_lo, *wp_hi, *wp_lo;
    float *t1, *t2;
    cudaGetSymbolAddress((void**)&xt_hi, g_xt_hi); cudaGetSymbolAddress((void**)&xt_lo, g_xt_lo);
    cudaGetSymbolAddress((void**)&xf_hi, g_xf_hi); cudaGetSymbolAddress((void**)&xf_lo, g_xf_lo);
    cudaGetSymbolAddress((void**)&q1h, g_q1h); cudaGetSymbolAddress((void**)&q1l, g_q1l);
    cudaGetSymbolAddress((void**)&k1h, g_k1h); cudaGetSymbolAddress((void**)&k1l, g_k1l);
    cudaGetSymbolAddress((void**)&v1h, g_v1h); cudaGetSymbolAddress((void**)&v1l, g_v1l);
    cudaGetSymbolAddress((void**)&q2h, g_q2h); cudaGetSymbolAddress((void**)&q2l, g_q2l);
    cudaGetSymbolAddress((void**)&k2h, g_k2h); cudaGetSymbolAddress((void**)&k2l, g_k2l);
    cudaGetSymbolAddress((void**)&v2h, g_v2h); cudaGetSymbolAddress((void**)&v2l, g_v2l);
    cudaGetSymbolAddress((void**)&a1h, g_a1h); cudaGetSymbolAddress((void**)&a1l, g_a1l);
    cudaGetSymbolAddress((void**)&a2h, g_a2h); cudaGetSymbolAddress((void**)&a2l, g_a2l);
    cudaGetSymbolAddress((void**)&cat_hi, g_cat_hi); cudaGetSymbolAddress((void**)&cat_lo, g_cat_lo);
    cudaGetSymbolAddress((void**)&wp_hi, g_wp_hi); cudaGetSymbolAddress((void**)&wp_lo, g_wp_lo);
    cudaGetSymbolAddress((void**)&t1, g_t1); cudaGetSymbolAddress((void**)&t2, g_t2);

    cudaFuncSetAttribute(tgemm_qkv, cudaFuncAttributeMaxDynamicSharedMemorySize, TG_SMEM);
    cudaFuncSetAttribute(tgemm_o,   cudaFuncAttributeMaxDynamicSharedMemorySize, TG_SMEM);
    cudaFuncSetAttribute(tgemm<2>,  cudaFuncAttributeMaxDynamicSharedMemorySize, TG_SMEM);
    cudaFuncSetAttribute(tgemm<3>,  cudaFuncAttributeMaxDynamicSharedMemorySize, TG_SMEM);
    cudaFuncSetAttribute(attn_mma,  cudaFuncAttributeMaxDynamicSharedMemorySize, AT_SMEM);

    const int nblk = (M_TOK * D_MODEL) / 1024;
    const dim3 tgrid(1024 / 32, 1024 / 32);
    const dim3 tgrid1(1024 / 32, 2048 / 32);
    const dim3 tblk(32, 8);
    const dim3 qkvgrid(3072 / 128, M_TOK / 128);     // (24, 64)
    const dim3 ggrid(D_MODEL / 128, M_TOK / 128);    // (8, 64)
    const dim3 ogrid(D_MODEL / 128, M_TOK / 128, 2); // (8, 64, 2)
    const dim3 agrid(SEQ / 64, N_HEADS, 2 * BATCH);  // (32, 16, 8)
    const dim3 lngrid(M_TOK, 2);

    // ---- conversions ----
    split_kernel<<<nblk, 256>>>(temporal, xt_hi, xt_lo);
    split_kernel<<<nblk, 256>>>(feature,  xf_hi, xf_lo);
    wconv<<<tgrid, tblk>>>(qt_w, wp_hi + WOFF_QT, wp_lo + WOFF_QT, 1024, 1024);
    wconv<<<tgrid, tblk>>>(kt_w, wp_hi + WOFF_KT, wp_lo + WOFF_KT, 1024, 1024);
    wconv<<<tgrid, tblk>>>(vt_w, wp_hi + WOFF_VT, wp_lo + WOFF_VT, 1024, 1024);
    wconv<<<tgrid, tblk>>>(qf_w, wp_hi + WOFF_QF, wp_lo + WOFF_QF, 1024, 1024);
    wconv<<<tgrid, tblk>>>(kf_w, wp_hi + WOFF_KF, wp_lo + WOFF_KF, 1024, 1024);
    wconv<<<tgrid, tblk>>>(vf_w, wp_hi + WOFF_VF, wp_lo + WOFF_VF, 1024, 1024);
    wconv<<<tgrid, tblk>>>(ot_w, wp_hi + WOFF_OT, wp_lo + WOFF_OT, 1024, 1024);
    wconv<<<tgrid, tblk>>>(of_w, wp_hi + WOFF_OF, wp_lo + WOFF_OF, 1024, 1024);
    wconv<<<tgrid, tblk>>>(fus2_w, wp_hi + WOFF_F2, wp_lo + WOFF_F2, 1024, 1024);
    wconv<<<tgrid1, tblk>>>(fus1_w, wp_hi + WOFF_F1, wp_lo + WOFF_F1, 2048, 1024);

    // ---- fused QKV projections ----
    // temporal -> Qt(attn1 Q), Kt/Vt(attn2 K,V)
    tgemm_qkv<<<qkvgrid, 256, TG_SMEM>>>(xt_hi, xt_lo, wp_hi + WOFF_QT, wp_lo + WOFF_QT,
                                         qt_b, kt_b, vt_b,
                                         q1h, q1l, k2h, k2l, v2h, v2l);
    // feature -> Qf(attn2 Q), Kf/Vf(attn1 K,V)
    tgemm_qkv<<<qkvgrid, 256, TG_SMEM>>>(xf_hi, xf_lo, wp_hi + WOFF_QF, wp_lo + WOFF_QF,
                                         qf_b, kf_b, vf_b,
                                         q2h, q2l, k1h, k1l, v1h, v1l);

    // ---- both attentions in one launch ----
    attn_mma<<<agrid, 128, AT_SMEM>>>(q1h, q1l, k1h, k1l, v1h, v1l, a1h, a1l,
                                      q2h, q2l, k2h, k2l, v2h, v2l, a2h, a2l);

    // ---- both O-projections in one launch ----
    tgemm_o<<<ogrid, 256, TG_SMEM>>>(a1h, a1l, a2h, a2l, wp_hi + WOFF_OT, wp_lo + WOFF_OT,
                                     ot_b, of_b, temporal, feature, t1, t2);

    // ---- both post-attn LayerNorms in one launch ----
    ln2_kernel<<<lngrid, 256>>>(t1, t2, ln_t_w, ln_t_b, ln_f_w, ln_f_b, cat_hi, cat_lo);

    // ---- fusion MLP ----
    tgemm<2><<<ggrid, 256, TG_SMEM>>>(cat_hi, cat_lo, wp_hi + WOFF_F1, wp_lo + WOFF_F1,
                                      fus1_b, nullptr, q1h, q1l, 2 * D_MODEL);
    tgemm<3><<<ggrid, 256, TG_SMEM>>>(q1h, q1l, wp_hi + WOFF_F2, wp_lo + WOFF_F2,
                                      fus2_b, t1, nullptr, nullptr, D_MODEL);
    ln_final<<<M_TOK, 256>>>(t1, ln_fus_w, ln_fus_b, out);
}